// round 6
// baseline (speedup 1.0000x reference)
#include <cuda_runtime.h>
#include <math.h>

#define BATCH 8192
#define CTX   168
#define SP    24
#define HIST  336
#define NC    128
#define NSEG  7
#define NROWS (BATCH*SP)     /* 196608 */
#define INDIM 30
#define QDIM  180

/* ------------------------------------------------------------------ */
/* scratch (device globals; allocation-free per harness rules)         */
/* ------------------------------------------------------------------ */
__device__ float g_inputs[BATCH*CTX*INDIM];   /* (B,168,30)  */
__device__ float g_gi[NROWS*384];
__device__ float g_gh[NROWS*384];
__device__ float g_hv[NROWS*NC];
__device__ float g_xw[NROWS*512];
__device__ float g_enc[NROWS*NC];             /* LSTM ys / GRU hidden */
__device__ float g_query[NROWS*QDIM];
__device__ float g_dec[NROWS*NC];
__device__ float g_h0[BATCH*NC];
__device__ float g_h1[BATCH*NC];
__device__ float g_c[BATCH*NC];
__device__ float g_scale[BATCH];
__device__ float g_wsum[BATCH];
__device__ float g_wcnt[BATCH];
__device__ float g_static[BATCH*18];
__device__ float g_tot[2];

__device__ __forceinline__ float sigm(float x){ return 1.0f/(1.0f+expf(-x)); }

/* ------------------------------------------------------------------ */
/* init: zero totals, h0, c, enc                                       */
/* ------------------------------------------------------------------ */
__global__ void init_zero()
{
    long i = (long)blockIdx.x*blockDim.x + threadIdx.x;
    if (i < 2)            g_tot[i] = 0.0f;
    if (i < BATCH*NC)   { g_h0[i] = 0.0f; g_c[i] = 0.0f; }
    if (i < (long)NROWS*NC) g_enc[i] = 0.0f;
}

/* ------------------------------------------------------------------ */
/* per-row |target| stats over the last CTX steps; global totals       */
/* ------------------------------------------------------------------ */
__global__ void row_stats(const float* __restrict__ pt,
                          const float* __restrict__ pov)
{
    int b    = blockIdx.x*8 + (threadIdx.x >> 5);
    int lane = threadIdx.x & 31;
    float ws = 0.0f, wc = 0.0f;
    for (int t = lane; t < CTX; t += 32) {
        float w = pov[b*HIST + CTX + t];
        float d = pt [b*HIST + CTX + t];
        ws += fabsf(d)*w;  wc += w;
    }
    #pragma unroll
    for (int o = 16; o; o >>= 1) {
        ws += __shfl_down_sync(0xffffffffu, ws, o);
        wc += __shfl_down_sync(0xffffffffu, wc, o);
    }
    if (lane == 0) {
        g_wsum[b] = ws;  g_wcnt[b] = wc;
        atomicAdd(&g_tot[0], ws);
        atomicAdd(&g_tot[1], wc);
    }
}

/* ------------------------------------------------------------------ */
/* finalize scale, build static features and (B,168,30) input tensor   */
/* ------------------------------------------------------------------ */
__global__ void build_inputs(const int*   __restrict__ cat,
                             const float* __restrict__ sreal,
                             const float* __restrict__ ptf,
                             const float* __restrict__ pt,
                             const float* __restrict__ emb)
{
    int b = blockIdx.x;
    __shared__ float s_scale;
    __shared__ float s_static[18];
    if (threadIdx.x == 0) {
        float ws  = g_wsum[b], wc = g_wcnt[b];
        float def = g_tot[0] / fmaxf(g_tot[1], 1.0f);
        float sc  = ws / fmaxf(wc, 1.0f);
        sc = (ws > 0.0f) ? sc : def;
        sc = fmaxf(1e-10f, sc);
        s_scale = sc;  g_scale[b] = sc;
    }
    __syncthreads();
    if (threadIdx.x < 18) {
        int c = threadIdx.x;  float v;
        if (c < 16)      v = emb[cat[b]*16 + c];
        else if (c == 16) v = sreal[b];
        else              v = logf(s_scale);
        s_static[c] = v;  g_static[b*18 + c] = v;
    }
    __syncthreads();
    float inv = 1.0f / s_scale;
    const int lagv[8] = {24,48,72,96,120,144,168,0};
    for (int t = threadIdx.x; t < CTX; t += blockDim.x) {
        float* o = &g_inputs[(b*CTX + t)*INDIM];
        #pragma unroll
        for (int l = 0; l < 8; l++)
            o[l] = pt[b*HIST + (CTX - lagv[l]) + t]*inv;
        #pragma unroll
        for (int f = 0; f < 4; f++)
            o[8+f] = ptf[(b*HIST + CTX + t)*4 + f];
        #pragma unroll
        for (int c = 0; c < 18; c++)
            o[12+c] = s_static[c];
    }
}

/* ------------------------------------------------------------------ */
/* generic fp32 GEMM:  C[r][n] = dot(A_row(r), W[n]) + bias[n]         */
/* A row address: A + (r/24)*aOuter + (r%24)*aInner + aOff             */
/* BM=64, BN=128, BK=16, 128 threads, 8x8 microtile                    */
/* M multiple of 64, N multiple of 128 (guaranteed by shapes)          */
/* ------------------------------------------------------------------ */
__global__ __launch_bounds__(128) void gemm_bias(
    const float* __restrict__ A, int aOuter, int aInner, int aOff,
    const float* __restrict__ W, const float* __restrict__ bias,
    float* __restrict__ C, int N, int K)
{
    __shared__ float As[64][17];
    __shared__ float Ws[16][132];
    __shared__ int   rowOff[64];

    int tid = threadIdx.x;
    int m0  = blockIdx.x*64;
    int n0  = blockIdx.y*128;
    if (tid < 64) {
        int m = m0 + tid;
        rowOff[tid] = (m/24)*aOuter + (m%24)*aInner + aOff;
    }
    __syncthreads();

    int ty = tid >> 4, tx = tid & 15;
    int lk = tid & 15, lm = tid >> 4;

    float acc[8][8];
    #pragma unroll
    for (int i = 0; i < 8; i++)
        #pragma unroll
        for (int j = 0; j < 8; j++) acc[i][j] = 0.0f;

    for (int k0 = 0; k0 < K; k0 += 16) {
        #pragma unroll
        for (int i = 0; i < 8; i++) {
            int mm = lm + i*8;
            int k  = k0 + lk;
            As[mm][lk] = (k < K) ? A[rowOff[mm] + k] : 0.0f;
        }
        #pragma unroll
        for (int i = 0; i < 16; i++) {
            int cc = lm + i*8;
            int k  = k0 + lk;
            Ws[lk][cc] = (k < K) ? W[(size_t)(n0+cc)*K + k] : 0.0f;
        }
        __syncthreads();
        #pragma unroll
        for (int kk = 0; kk < 16; kk++) {
            float a[8];
            #pragma unroll
            for (int i = 0; i < 8; i++) a[i] = As[ty*8+i][kk];
            float4 w0 = *(const float4*)&Ws[kk][tx*8];
            float4 w1 = *(const float4*)&Ws[kk][tx*8+4];
            float w[8] = {w0.x,w0.y,w0.z,w0.w,w1.x,w1.y,w1.z,w1.w};
            #pragma unroll
            for (int i = 0; i < 8; i++)
                #pragma unroll
                for (int j = 0; j < 8; j++)
                    acc[i][j] = fmaf(a[i], w[j], acc[i][j]);
        }
        __syncthreads();
    }

    float bv[8];
    #pragma unroll
    for (int j = 0; j < 8; j++) bv[j] = bias[n0 + tx*8 + j];
    #pragma unroll
    for (int i = 0; i < 8; i++) {
        int m = m0 + ty*8 + i;
        float4 s0, s1;
        s0.x = acc[i][0]+bv[0]; s0.y = acc[i][1]+bv[1];
        s0.z = acc[i][2]+bv[2]; s0.w = acc[i][3]+bv[3];
        s1.x = acc[i][4]+bv[4]; s1.y = acc[i][5]+bv[5];
        s1.z = acc[i][6]+bv[6]; s1.w = acc[i][7]+bv[7];
        *(float4*)&C[(size_t)m*N + n0 + tx*8]     = s0;
        *(float4*)&C[(size_t)m*N + n0 + tx*8 + 4] = s1;
    }
}

/* ------------------------------------------------------------------ */
/* GRU gate combine: hv = (1-z)*n + z*h                                */
/* ------------------------------------------------------------------ */
__global__ void gru_combine()
{
    int idx = blockIdx.x*blockDim.x + threadIdx.x;
    if (idx >= NROWS*NC) return;
    int r = idx >> 7, j = idx & 127;
    const float* gi = &g_gi[(size_t)r*384];
    const float* gh = &g_gh[(size_t)r*384];
    float rg = sigm(gi[j]       + gh[j]);
    float z  = sigm(gi[128 + j] + gh[128 + j]);
    float n  = tanhf(gi[256 + j] + rg*gh[256 + j]);
    float h  = g_enc[idx];
    g_hv[idx] = (1.0f - z)*n + z*h;
}

/* ------------------------------------------------------------------ */
/* fused LSTM step: gates = xw[:,t,:] + h @ Whh^T ; cell update        */
/* block = 64 batch rows x 1 unit-group (32 units -> 128 gate cols)    */
/* ------------------------------------------------------------------ */
__global__ __launch_bounds__(128) void lstm_step(
    const float* __restrict__ Whh,   /* 512x128 */
    const float* __restrict__ hin,   /* B x 128 */
    float*       __restrict__ hout,  /* B x 128 */
    float*       __restrict__ ys,    /* NROWS x 128 */
    int t)
{
    __shared__ float As[64][17];
    __shared__ float Ws[16][132];
    __shared__ float G[64][128];

    int tid = threadIdx.x;
    int b0  = blockIdx.x*64;
    int ug  = blockIdx.y;            /* 0..3 */
    int ty = tid >> 4, tx = tid & 15;
    int lk = tid & 15, lm = tid >> 4;

    float acc[8][8];
    #pragma unroll
    for (int i = 0; i < 8; i++) {
        int r = (b0 + ty*8 + i)*SP + t;
        #pragma unroll
        for (int j = 0; j < 8; j++) {
            int cc = tx*8 + j;
            int g  = ((cc >> 5) << 7) + ug*32 + (cc & 31);
            acc[i][j] = g_xw[(size_t)r*512 + g];
        }
    }

    for (int k0 = 0; k0 < 128; k0 += 16) {
        #pragma unroll
        for (int i = 0; i < 8; i++) {
            int mm = lm + i*8;
            As[mm][lk] = hin[(b0+mm)*NC + k0 + lk];
        }
        #pragma unroll
        for (int i = 0; i < 16; i++) {
            int cc = lm + i*8;
            int g  = ((cc >> 5) << 7) + ug*32 + (cc & 31);
            Ws[lk][cc] = Whh[g*NC + k0 + lk];
        }
        __syncthreads();
        #pragma unroll
        for (int kk = 0; kk < 16; kk++) {
            float a[8];
            #pragma unroll
            for (int i = 0; i < 8; i++) a[i] = As[ty*8+i][kk];
            float4 w0 = *(const float4*)&Ws[kk][tx*8];
            float4 w1 = *(const float4*)&Ws[kk][tx*8+4];
            float w[8] = {w0.x,w0.y,w0.z,w0.w,w1.x,w1.y,w1.z,w1.w};
            #pragma unroll
            for (int i = 0; i < 8; i++)
                #pragma unroll
                for (int j = 0; j < 8; j++)
                    acc[i][j] = fmaf(a[i], w[j], acc[i][j]);
        }
        __syncthreads();
    }

    #pragma unroll
    for (int i = 0; i < 8; i++)
        #pragma unroll
        for (int j = 0; j < 8; j++)
            G[ty*8+i][tx*8+j] = acc[i][j];
    __syncthreads();

    for (int u = tid; u < 64*32; u += 128) {
        int row = u >> 5, jl = u & 31;
        int j = ug*32 + jl;
        int b = b0 + row;
        float ig = G[row][jl];
        float fg = G[row][32 + jl];
        float gg = G[row][64 + jl];
        float og = G[row][96 + jl];
        float cold = g_c[b*NC + j];
        float cn = sigm(fg)*cold + sigm(ig)*tanhf(gg);
        float hn = sigm(og)*tanhf(cn);
        g_c[b*NC + j] = cn;
        hout[b*NC + j] = hn;
        ys[(size_t)(b*SP + t)*NC + j] = hn;
    }
}

/* ------------------------------------------------------------------ */
/* decoder query assembly: [inputs_seg0(30) | enc(128) | ftf(4) | st(18)] */
/* ------------------------------------------------------------------ */
__global__ void build_query(const float* __restrict__ ftf)
{
    long idx = (long)blockIdx.x*blockDim.x + threadIdx.x;
    if (idx >= (long)NROWS*QDIM) return;
    int r = (int)(idx/QDIM), c = (int)(idx%QDIM);
    int b = r/SP, t = r%SP;
    float v;
    if      (c < 30)  v = g_inputs[(b*CTX + t)*INDIM + c];
    else if (c < 158) v = g_enc[(size_t)r*NC + (c-30)];
    else if (c < 162) v = ftf[r*4 + (c-158)];
    else              v = g_static[b*18 + (c-162)];
    g_query[idx] = v;
}

/* ------------------------------------------------------------------ */
/* output projection + rescale                                         */
/* ------------------------------------------------------------------ */
__global__ void out_kernel(const float* __restrict__ oW,
                           const float* __restrict__ ob,
                           float* __restrict__ out)
{
    int r    = blockIdx.x*8 + (threadIdx.x >> 5);
    int lane = threadIdx.x & 31;
    float s = 0.0f;
    #pragma unroll
    for (int k = 0; k < 4; k++)
        s += g_dec[(size_t)r*NC + lane + 32*k]*oW[lane + 32*k];
    #pragma unroll
    for (int o = 16; o; o >>= 1) s += __shfl_down_sync(0xffffffffu, s, o);
    if (lane == 0)
        out[r] = (s + ob[0])*g_scale[r/SP];
}

/* ------------------------------------------------------------------ */
/* host driver                                                         */
/* ------------------------------------------------------------------ */
extern "C" void kernel_launch(void* const* d_in, const int* in_sizes, int n_in,
                              void* d_out, int out_size)
{
    const int*   cat   = (const int*)  d_in[0];
    const float* sreal = (const float*)d_in[1];
    const float* ptf   = (const float*)d_in[2];
    const float* pt    = (const float*)d_in[3];
    const float* pov   = (const float*)d_in[4];
    const float* ftf   = (const float*)d_in[5];
    const float* emb   = (const float*)d_in[6];
    const float* gWih  = (const float*)d_in[7];
    const float* gWhh  = (const float*)d_in[8];
    const float* gbih  = (const float*)d_in[9];
    const float* gbhh  = (const float*)d_in[10];
    const float* eWih  = (const float*)d_in[11];
    const float* eWhh  = (const float*)d_in[12];
    const float* eb    = (const float*)d_in[13];
    const float* dWih  = (const float*)d_in[14];
    const float* dWhh  = (const float*)d_in[15];
    const float* db    = (const float*)d_in[16];
    const float* oW    = (const float*)d_in[17];
    const float* ob    = (const float*)d_in[18];
    float* out = (float*)d_out;

    float *p_inputs, *p_gi, *p_gh, *p_hv, *p_xw, *p_enc, *p_query, *p_dec, *p_h0, *p_h1;
    cudaGetSymbolAddress((void**)&p_inputs, g_inputs);
    cudaGetSymbolAddress((void**)&p_gi,     g_gi);
    cudaGetSymbolAddress((void**)&p_gh,     g_gh);
    cudaGetSymbolAddress((void**)&p_hv,     g_hv);
    cudaGetSymbolAddress((void**)&p_xw,     g_xw);
    cudaGetSymbolAddress((void**)&p_enc,    g_enc);
    cudaGetSymbolAddress((void**)&p_query,  g_query);
    cudaGetSymbolAddress((void**)&p_dec,    g_dec);
    cudaGetSymbolAddress((void**)&p_h0,     g_h0);
    cudaGetSymbolAddress((void**)&p_h1,     g_h1);
    float* hb[2] = {p_h0, p_h1};

    init_zero<<<(NROWS*NC + 255)/256, 256>>>();
    row_stats<<<BATCH/8, 256>>>(pt, pov);
    build_inputs<<<BATCH, 192>>>(cat, sreal, ptf, pt, emb);

    dim3 gThr(128);
    for (int i = 0; i < NSEG; i++) {
        /* gi = x @ gru_Wih^T + bih   (x = inputs segment i, K=30) */
        gemm_bias<<<dim3(NROWS/64, 3), gThr>>>(p_inputs, CTX*INDIM, INDIM,
                                               i*SP*INDIM, gWih, gbih,
                                               p_gi, 384, 30);
        /* gh = h @ gru_Whh^T + bhh   (h = previous enc ys) */
        gemm_bias<<<dim3(NROWS/64, 3), gThr>>>(p_enc, SP*NC, NC, 0,
                                               gWhh, gbhh, p_gh, 384, 128);
        gru_combine<<<(NROWS*NC + 255)/256, 256>>>();
        /* xw = hv @ enc_Wih[i]^T + enc_b[i] */
        gemm_bias<<<dim3(NROWS/64, 4), gThr>>>(p_hv, SP*NC, NC, 0,
                                               eWih + (size_t)i*512*128,
                                               eb + i*512, p_xw, 512, 128);
        for (int t = 0; t < SP; t++)
            lstm_step<<<dim3(BATCH/64, 4), gThr>>>(eWhh + (size_t)i*512*128,
                                                   hb[t & 1], hb[(t & 1) ^ 1],
                                                   p_enc, t);
    }

    build_query<<<(int)(((long)NROWS*QDIM + 255)/256), 256>>>(ftf);
    gemm_bias<<<dim3(NROWS/64, 4), gThr>>>(p_query, SP*QDIM, QDIM, 0,
                                           dWih, db, p_xw, 512, 180);
    for (int t = 0; t < SP; t++)
        lstm_step<<<dim3(BATCH/64, 4), gThr>>>(dWhh, hb[t & 1], hb[(t & 1) ^ 1],
                                               p_dec, t);

    out_kernel<<<NROWS/8, 256>>>(oW, ob, out);
}

// round 7
// speedup vs baseline: 1.0013x; 1.0013x over previous
#include <cuda_runtime.h>
#include <math.h>

#define BATCH 8192
#define CTX   168
#define SP    24
#define HIST  336
#define NC    128
#define NSEG  7
#define NROWS (BATCH*SP)     /* 196608 */
#define INDIM 30
#define QDIM  180

/* ------------------------------------------------------------------ */
/* scratch (device globals; allocation-free per harness rules)         */
/* ------------------------------------------------------------------ */
__device__ float g_inputs[BATCH*CTX*INDIM];   /* (B,168,30)  */
__device__ float g_gi[NROWS*384];
__device__ float g_gh[NROWS*384];
__device__ float g_hv[NROWS*NC];
__device__ float g_xw[NROWS*512];
__device__ float g_enc[NROWS*NC];             /* LSTM ys / GRU hidden */
__device__ float g_query[NROWS*QDIM];
__device__ float g_dec[NROWS*NC];
__device__ float g_h0[BATCH*NC];
__device__ float g_h1[BATCH*NC];
__device__ float g_c[BATCH*NC];
__device__ float g_scale[BATCH];
__device__ float g_wsum[BATCH];
__device__ float g_wcnt[BATCH];
__device__ float g_static[BATCH*18];
__device__ float g_tot[2];

__device__ __forceinline__ float sigm(float x){ return 1.0f/(1.0f+expf(-x)); }

/* ------------------------------------------------------------------ */
/* init: zero totals, h0, c, enc                                       */
/* ------------------------------------------------------------------ */
__global__ void init_zero()
{
    long i = (long)blockIdx.x*blockDim.x + threadIdx.x;
    if (i < 2)            g_tot[i] = 0.0f;
    if (i < BATCH*NC)   { g_h0[i] = 0.0f; g_c[i] = 0.0f; }
    if (i < (long)NROWS*NC) g_enc[i] = 0.0f;
}

/* ------------------------------------------------------------------ */
/* per-row |target| stats over the last CTX steps; global totals       */
/* ------------------------------------------------------------------ */
__global__ void row_stats(const float* __restrict__ pt,
                          const float* __restrict__ pov)
{
    int b    = blockIdx.x*8 + (threadIdx.x >> 5);
    int lane = threadIdx.x & 31;
    float ws = 0.0f, wc = 0.0f;
    for (int t = lane; t < CTX; t += 32) {
        float w = pov[b*HIST + CTX + t];
        float d = pt [b*HIST + CTX + t];
        ws += fabsf(d)*w;  wc += w;
    }
    #pragma unroll
    for (int o = 16; o; o >>= 1) {
        ws += __shfl_down_sync(0xffffffffu, ws, o);
        wc += __shfl_down_sync(0xffffffffu, wc, o);
    }
    if (lane == 0) {
        g_wsum[b] = ws;  g_wcnt[b] = wc;
        atomicAdd(&g_tot[0], ws);
        atomicAdd(&g_tot[1], wc);
    }
}

/* ------------------------------------------------------------------ */
/* finalize scale, build static features and (B,168,30) input tensor   */
/* ------------------------------------------------------------------ */
__global__ void build_inputs(const int*   __restrict__ cat,
                             const float* __restrict__ sreal,
                             const float* __restrict__ ptf,
                             const float* __restrict__ pt,
                             const float* __restrict__ emb)
{
    int b = blockIdx.x;
    __shared__ float s_scale;
    __shared__ float s_static[18];
    if (threadIdx.x == 0) {
        float ws  = g_wsum[b], wc = g_wcnt[b];
        float def = g_tot[0] / fmaxf(g_tot[1], 1.0f);
        float sc  = ws / fmaxf(wc, 1.0f);
        sc = (ws > 0.0f) ? sc : def;
        sc = fmaxf(1e-10f, sc);
        s_scale = sc;  g_scale[b] = sc;
    }
    __syncthreads();
    if (threadIdx.x < 18) {
        int c = threadIdx.x;  float v;
        if (c < 16)      v = emb[cat[b]*16 + c];
        else if (c == 16) v = sreal[b];
        else              v = logf(s_scale);
        s_static[c] = v;  g_static[b*18 + c] = v;
    }
    __syncthreads();
    float inv = 1.0f / s_scale;
    const int lagv[8] = {24,48,72,96,120,144,168,0};
    for (int t = threadIdx.x; t < CTX; t += blockDim.x) {
        float* o = &g_inputs[(b*CTX + t)*INDIM];
        #pragma unroll
        for (int l = 0; l < 8; l++)
            o[l] = pt[b*HIST + (CTX - lagv[l]) + t]*inv;
        #pragma unroll
        for (int f = 0; f < 4; f++)
            o[8+f] = ptf[(b*HIST + CTX + t)*4 + f];
        #pragma unroll
        for (int c = 0; c < 18; c++)
            o[12+c] = s_static[c];
    }
}

/* ------------------------------------------------------------------ */
/* generic fp32 GEMM:  C[r][n] = dot(A_row(r), W[n]) + bias[n]         */
/* A row address: A + (r/24)*aOuter + (r%24)*aInner + aOff             */
/* BM=64, BN=128, BK=16, 128 threads, 8x8 microtile                    */
/* M multiple of 64, N multiple of 128 (guaranteed by shapes)          */
/* ------------------------------------------------------------------ */
__global__ __launch_bounds__(128) void gemm_bias(
    const float* __restrict__ A, int aOuter, int aInner, int aOff,
    const float* __restrict__ W, const float* __restrict__ bias,
    float* __restrict__ C, int N, int K)
{
    __shared__ float As[64][17];
    __shared__ float Ws[16][132];
    __shared__ int   rowOff[64];

    int tid = threadIdx.x;
    int m0  = blockIdx.x*64;
    int n0  = blockIdx.y*128;
    if (tid < 64) {
        int m = m0 + tid;
        rowOff[tid] = (m/24)*aOuter + (m%24)*aInner + aOff;
    }
    __syncthreads();

    int ty = tid >> 4, tx = tid & 15;
    int lk = tid & 15, lm = tid >> 4;

    float acc[8][8];
    #pragma unroll
    for (int i = 0; i < 8; i++)
        #pragma unroll
        for (int j = 0; j < 8; j++) acc[i][j] = 0.0f;

    for (int k0 = 0; k0 < K; k0 += 16) {
        #pragma unroll
        for (int i = 0; i < 8; i++) {
            int mm = lm + i*8;
            int k  = k0 + lk;
            As[mm][lk] = (k < K) ? A[rowOff[mm] + k] : 0.0f;
        }
        #pragma unroll
        for (int i = 0; i < 16; i++) {
            int cc = lm + i*8;
            int k  = k0 + lk;
            Ws[lk][cc] = (k < K) ? W[(size_t)(n0+cc)*K + k] : 0.0f;
        }
        __syncthreads();
        #pragma unroll
        for (int kk = 0; kk < 16; kk++) {
            float a[8];
            #pragma unroll
            for (int i = 0; i < 8; i++) a[i] = As[ty*8+i][kk];
            float4 w0 = *(const float4*)&Ws[kk][tx*8];
            float4 w1 = *(const float4*)&Ws[kk][tx*8+4];
            float w[8] = {w0.x,w0.y,w0.z,w0.w,w1.x,w1.y,w1.z,w1.w};
            #pragma unroll
            for (int i = 0; i < 8; i++)
                #pragma unroll
                for (int j = 0; j < 8; j++)
                    acc[i][j] = fmaf(a[i], w[j], acc[i][j]);
        }
        __syncthreads();
    }

    float bv[8];
    #pragma unroll
    for (int j = 0; j < 8; j++) bv[j] = bias[n0 + tx*8 + j];
    #pragma unroll
    for (int i = 0; i < 8; i++) {
        int m = m0 + ty*8 + i;
        float4 s0, s1;
        s0.x = acc[i][0]+bv[0]; s0.y = acc[i][1]+bv[1];
        s0.z = acc[i][2]+bv[2]; s0.w = acc[i][3]+bv[3];
        s1.x = acc[i][4]+bv[4]; s1.y = acc[i][5]+bv[5];
        s1.z = acc[i][6]+bv[6]; s1.w = acc[i][7]+bv[7];
        *(float4*)&C[(size_t)m*N + n0 + tx*8]     = s0;
        *(float4*)&C[(size_t)m*N + n0 + tx*8 + 4] = s1;
    }
}

/* ------------------------------------------------------------------ */
/* GRU gate combine: hv = (1-z)*n + z*h                                */
/* ------------------------------------------------------------------ */
__global__ void gru_combine()
{
    int idx = blockIdx.x*blockDim.x + threadIdx.x;
    if (idx >= NROWS*NC) return;
    int r = idx >> 7, j = idx & 127;
    const float* gi = &g_gi[(size_t)r*384];
    const float* gh = &g_gh[(size_t)r*384];
    float rg = sigm(gi[j]       + gh[j]);
    float z  = sigm(gi[128 + j] + gh[128 + j]);
    float n  = tanhf(gi[256 + j] + rg*gh[256 + j]);
    float h  = g_enc[idx];
    g_hv[idx] = (1.0f - z)*n + z*h;
}

/* ------------------------------------------------------------------ */
/* fused LSTM step: gates = xw[:,t,:] + h @ Whh^T ; cell update        */
/* block = 64 batch rows x 1 unit-group (32 units -> 128 gate cols)    */
/* ------------------------------------------------------------------ */
__global__ __launch_bounds__(128) void lstm_step(
    const float* __restrict__ Whh,   /* 512x128 */
    const float* __restrict__ hin,   /* B x 128 */
    float*       __restrict__ hout,  /* B x 128 */
    float*       __restrict__ ys,    /* NROWS x 128 */
    int t)
{
    __shared__ float As[64][17];
    __shared__ float Ws[16][132];
    __shared__ float G[64][128];

    int tid = threadIdx.x;
    int b0  = blockIdx.x*64;
    int ug  = blockIdx.y;            /* 0..3 */
    int ty = tid >> 4, tx = tid & 15;
    int lk = tid & 15, lm = tid >> 4;

    float acc[8][8];
    #pragma unroll
    for (int i = 0; i < 8; i++) {
        int r = (b0 + ty*8 + i)*SP + t;
        #pragma unroll
        for (int j = 0; j < 8; j++) {
            int cc = tx*8 + j;
            int g  = ((cc >> 5) << 7) + ug*32 + (cc & 31);
            acc[i][j] = g_xw[(size_t)r*512 + g];
        }
    }

    for (int k0 = 0; k0 < 128; k0 += 16) {
        #pragma unroll
        for (int i = 0; i < 8; i++) {
            int mm = lm + i*8;
            As[mm][lk] = hin[(b0+mm)*NC + k0 + lk];
        }
        #pragma unroll
        for (int i = 0; i < 16; i++) {
            int cc = lm + i*8;
            int g  = ((cc >> 5) << 7) + ug*32 + (cc & 31);
            Ws[lk][cc] = Whh[g*NC + k0 + lk];
        }
        __syncthreads();
        #pragma unroll
        for (int kk = 0; kk < 16; kk++) {
            float a[8];
            #pragma unroll
            for (int i = 0; i < 8; i++) a[i] = As[ty*8+i][kk];
            float4 w0 = *(const float4*)&Ws[kk][tx*8];
            float4 w1 = *(const float4*)&Ws[kk][tx*8+4];
            float w[8] = {w0.x,w0.y,w0.z,w0.w,w1.x,w1.y,w1.z,w1.w};
            #pragma unroll
            for (int i = 0; i < 8; i++)
                #pragma unroll
                for (int j = 0; j < 8; j++)
                    acc[i][j] = fmaf(a[i], w[j], acc[i][j]);
        }
        __syncthreads();
    }

    #pragma unroll
    for (int i = 0; i < 8; i++)
        #pragma unroll
        for (int j = 0; j < 8; j++)
            G[ty*8+i][tx*8+j] = acc[i][j];
    __syncthreads();

    for (int u = tid; u < 64*32; u += 128) {
        int row = u >> 5, jl = u & 31;
        int j = ug*32 + jl;
        int b = b0 + row;
        float ig = G[row][jl];
        float fg = G[row][32 + jl];
        float gg = G[row][64 + jl];
        float og = G[row][96 + jl];
        float cold = g_c[b*NC + j];
        float cn = sigm(fg)*cold + sigm(ig)*tanhf(gg);
        float hn = sigm(og)*tanhf(cn);
        g_c[b*NC + j] = cn;
        hout[b*NC + j] = hn;
        ys[(size_t)(b*SP + t)*NC + j] = hn;
    }
}

/* ------------------------------------------------------------------ */
/* decoder query assembly: [inputs_seg0(30) | enc(128) | ftf(4) | st(18)] */
/* ------------------------------------------------------------------ */
__global__ void build_query(const float* __restrict__ ftf)
{
    long idx = (long)blockIdx.x*blockDim.x + threadIdx.x;
    if (idx >= (long)NROWS*QDIM) return;
    int r = (int)(idx/QDIM), c = (int)(idx%QDIM);
    int b = r/SP, t = r%SP;
    float v;
    if      (c < 30)  v = g_inputs[(b*CTX + t)*INDIM + c];
    else if (c < 158) v = g_enc[(size_t)r*NC + (c-30)];
    else if (c < 162) v = ftf[r*4 + (c-158)];
    else              v = g_static[b*18 + (c-162)];
    g_query[idx] = v;
}

/* ------------------------------------------------------------------ */
/* output projection + rescale                                         */
/* ------------------------------------------------------------------ */
__global__ void out_kernel(const float* __restrict__ oW,
                           const float* __restrict__ ob,
                           float* __restrict__ out)
{
    int r    = blockIdx.x*8 + (threadIdx.x >> 5);
    int lane = threadIdx.x & 31;
    float s = 0.0f;
    #pragma unroll
    for (int k = 0; k < 4; k++)
        s += g_dec[(size_t)r*NC + lane + 32*k]*oW[lane + 32*k];
    #pragma unroll
    for (int o = 16; o; o >>= 1) s += __shfl_down_sync(0xffffffffu, s, o);
    if (lane == 0)
        out[r] = (s + ob[0])*g_scale[r/SP];
}

/* ------------------------------------------------------------------ */
/* host driver                                                         */
/* ------------------------------------------------------------------ */
extern "C" void kernel_launch(void* const* d_in, const int* in_sizes, int n_in,
                              void* d_out, int out_size)
{
    const int*   cat   = (const int*)  d_in[0];
    const float* sreal = (const float*)d_in[1];
    const float* ptf   = (const float*)d_in[2];
    const float* pt    = (const float*)d_in[3];
    const float* pov   = (const float*)d_in[4];
    const float* ftf   = (const float*)d_in[5];
    const float* emb   = (const float*)d_in[6];
    const float* gWih  = (const float*)d_in[7];
    const float* gWhh  = (const float*)d_in[8];
    const float* gbih  = (const float*)d_in[9];
    const float* gbhh  = (const float*)d_in[10];
    const float* eWih  = (const float*)d_in[11];
    const float* eWhh  = (const float*)d_in[12];
    const float* eb    = (const float*)d_in[13];
    const float* dWih  = (const float*)d_in[14];
    const float* dWhh  = (const float*)d_in[15];
    const float* db    = (const float*)d_in[16];
    const float* oW    = (const float*)d_in[17];
    const float* ob    = (const float*)d_in[18];
    float* out = (float*)d_out;

    float *p_inputs, *p_gi, *p_gh, *p_hv, *p_xw, *p_enc, *p_query, *p_dec, *p_h0, *p_h1;
    cudaGetSymbolAddress((void**)&p_inputs, g_inputs);
    cudaGetSymbolAddress((void**)&p_gi,     g_gi);
    cudaGetSymbolAddress((void**)&p_gh,     g_gh);
    cudaGetSymbolAddress((void**)&p_hv,     g_hv);
    cudaGetSymbolAddress((void**)&p_xw,     g_xw);
    cudaGetSymbolAddress((void**)&p_enc,    g_enc);
    cudaGetSymbolAddress((void**)&p_query,  g_query);
    cudaGetSymbolAddress((void**)&p_dec,    g_dec);
    cudaGetSymbolAddress((void**)&p_h0,     g_h0);
    cudaGetSymbolAddress((void**)&p_h1,     g_h1);
    float* hb[2] = {p_h0, p_h1};

    init_zero<<<(NROWS*NC + 255)/256, 256>>>();
    row_stats<<<BATCH/8, 256>>>(pt, pov);
    build_inputs<<<BATCH, 192>>>(cat, sreal, ptf, pt, emb);

    dim3 gThr(128);
    for (int i = 0; i < NSEG; i++) {
        /* gi = x @ gru_Wih^T + bih   (x = inputs segment i, K=30) */
        gemm_bias<<<dim3(NROWS/64, 3), gThr>>>(p_inputs, CTX*INDIM, INDIM,
                                               i*SP*INDIM, gWih, gbih,
                                               p_gi, 384, 30);
        /* gh = h @ gru_Whh^T + bhh   (h = previous enc ys) */
        gemm_bias<<<dim3(NROWS/64, 3), gThr>>>(p_enc, SP*NC, NC, 0,
                                               gWhh, gbhh, p_gh, 384, 128);
        gru_combine<<<(NROWS*NC + 255)/256, 256>>>();
        /* xw = hv @ enc_Wih[i]^T + enc_b[i] */
        gemm_bias<<<dim3(NROWS/64, 4), gThr>>>(p_hv, SP*NC, NC, 0,
                                               eWih + (size_t)i*512*128,
                                               eb + i*512, p_xw, 512, 128);
        for (int t = 0; t < SP; t++)
            lstm_step<<<dim3(BATCH/64, 4), gThr>>>(eWhh + (size_t)i*512*128,
                                                   hb[t & 1], hb[(t & 1) ^ 1],
                                                   p_enc, t);
    }

    build_query<<<(int)(((long)NROWS*QDIM + 255)/256), 256>>>(ftf);
    gemm_bias<<<dim3(NROWS/64, 4), gThr>>>(p_query, SP*QDIM, QDIM, 0,
                                           dWih, db, p_xw, 512, 180);
    for (int t = 0; t < SP; t++)
        lstm_step<<<dim3(BATCH/64, 4), gThr>>>(dWhh, hb[t & 1], hb[(t & 1) ^ 1],
                                               p_dec, t);

    out_kernel<<<NROWS/8, 256>>>(oW, ob, out);
}

// round 11
// speedup vs baseline: 1.1520x; 1.1506x over previous
#include <cuda_runtime.h>
#include <math.h>
#include <stdint.h>

#define BATCH 8192
#define CTX   168
#define SP    24
#define HIST  336
#define NC    128
#define NSEG  7
#define NROWS (BATCH*SP)
#define KCAT  160
#define KQ    180

/* scratch (device globals; allocation-free) */
__device__ float g_inputs[BATCH*CTX*30];
__device__ float g_xw[(size_t)NROWS*512];
__device__ float g_hv[(size_t)NROWS*NC];
__device__ float g_enc[(size_t)NROWS*NC];
__device__ float g_dec[(size_t)NROWS*NC];
__device__ float g_h0[BATCH*NC];
__device__ float g_h1[BATCH*NC];
__device__ float g_c[BATCH*NC];
__device__ float g_scale[BATCH];
__device__ float g_wsum[BATCH];
__device__ float g_wcnt[BATCH];
__device__ float g_static[BATCH*18];
__device__ float g_tot[2];
/* packed weights: row = unit*4 + gate */
__device__ float g_Wcat[512*KCAT];
__device__ float g_bcat[512];
__device__ float g_eWih[NSEG*512*NC];
__device__ float g_eWhh[NSEG*512*NC];
__device__ float g_eb[NSEG*512];
__device__ float g_dWih[512*KQ];
__device__ float g_dWhh[512*NC];
__device__ float g_db[512];

__device__ __forceinline__ float sigm(float x){ return 1.0f/(1.0f+expf(-x)); }
__device__ __forceinline__ uint32_t f2tf(float x){
    uint32_t r; asm("cvt.rna.tf32.f32 %0, %1;" : "=r"(r) : "f"(x)); return r;
}
__device__ __forceinline__ void mma8(float* c, const uint32_t* a, const uint32_t* b){
    asm volatile("mma.sync.aligned.m16n8k8.row.col.f32.tf32.tf32.f32 "
        "{%0,%1,%2,%3}, {%4,%5,%6,%7}, {%8,%9}, {%0,%1,%2,%3};\n"
        : "+f"(c[0]),"+f"(c[1]),"+f"(c[2]),"+f"(c[3])
        : "r"(a[0]),"r"(a[1]),"r"(a[2]),"r"(a[3]), "r"(b[0]),"r"(b[1]));
}

/* ---------------- setup ---------------- */
__global__ void init_zero()
{
    long i = (long)blockIdx.x*blockDim.x + threadIdx.x;
    if (i < 2)            g_tot[i] = 0.0f;
    if (i < BATCH*NC)   { g_h0[i] = 0.0f; g_c[i] = 0.0f; }
    if (i < (long)NROWS*NC) g_enc[i] = 0.0f;
}

__global__ void row_stats(const float* __restrict__ pt,
                          const float* __restrict__ pov)
{
    int b    = blockIdx.x*8 + (threadIdx.x >> 5);
    int lane = threadIdx.x & 31;
    float ws = 0.0f, wc = 0.0f;
    for (int t = lane; t < CTX; t += 32) {
        float w = pov[b*HIST + CTX + t];
        float d = pt [b*HIST + CTX + t];
        ws += fabsf(d)*w;  wc += w;
    }
    #pragma unroll
    for (int o = 16; o; o >>= 1) {
        ws += __shfl_down_sync(0xffffffffu, ws, o);
        wc += __shfl_down_sync(0xffffffffu, wc, o);
    }
    if (lane == 0) {
        g_wsum[b] = ws;  g_wcnt[b] = wc;
        atomicAdd(&g_tot[0], ws);
        atomicAdd(&g_tot[1], wc);
    }
}

__global__ void build_inputs(const int*   __restrict__ cat,
                             const float* __restrict__ sreal,
                             const float* __restrict__ ptf,
                             const float* __restrict__ pt,
                             const float* __restrict__ emb)
{
    int b = blockIdx.x;
    __shared__ float s_scale;
    __shared__ float s_static[18];
    if (threadIdx.x == 0) {
        float ws  = g_wsum[b], wc = g_wcnt[b];
        float def = g_tot[0] / fmaxf(g_tot[1], 1.0f);
        float sc  = ws / fmaxf(wc, 1.0f);
        sc = (ws > 0.0f) ? sc : def;
        sc = fmaxf(1e-10f, sc);
        s_scale = sc;  g_scale[b] = sc;
    }
    __syncthreads();
    if (threadIdx.x < 18) {
        int c = threadIdx.x;  float v;
        if (c < 16)       v = emb[cat[b]*16 + c];
        else if (c == 16) v = sreal[b];
        else              v = logf(s_scale);
        s_static[c] = v;  g_static[b*18 + c] = v;
    }
    __syncthreads();
    float inv = 1.0f / s_scale;
    const int lagv[8] = {24,48,72,96,120,144,168,0};
    for (int t = threadIdx.x; t < CTX; t += blockDim.x) {
        float* o = &g_inputs[(b*CTX + t)*30];
        #pragma unroll
        for (int l = 0; l < 8; l++)
            o[l] = pt[b*HIST + (CTX - lagv[l]) + t]*inv;
        #pragma unroll
        for (int f = 0; f < 4; f++)
            o[8+f] = ptf[(b*HIST + CTX + t)*4 + f];
        #pragma unroll
        for (int c = 0; c < 18; c++)
            o[12+c] = s_static[c];
    }
}

/* ---------------- weight packing (row = unit*4 + gate) ------------- */
__global__ void pack_gru(const float* __restrict__ gWih, const float* __restrict__ gWhh,
                         const float* __restrict__ gbih, const float* __restrict__ gbhh)
{
    int idx = blockIdx.x*blockDim.x + threadIdx.x;
    if (idx < 512) {
        int u = idx>>2, gg = idx&3;  float bv;
        if      (gg == 0) bv = gbih[u]     + gbhh[u];
        else if (gg == 1) bv = gbih[128+u] + gbhh[128+u];
        else if (gg == 2) bv = gbih[256+u];
        else              bv = gbhh[256+u];
        g_bcat[idx] = bv;
    }
    if (idx >= 512*KCAT) return;
    int pr = idx/KCAT, k = idx%KCAT;
    int u = pr>>2, gg = pr&3;
    float v = 0.0f;
    if (gg == 0) {
        if (k < 30)       v = gWih[u*30 + k];
        else if (k < 158) v = gWhh[u*128 + (k-30)];
    } else if (gg == 1) {
        if (k < 30)       v = gWih[(128+u)*30 + k];
        else if (k < 158) v = gWhh[(128+u)*128 + (k-30)];
    } else if (gg == 2) {
        if (k < 30)       v = gWih[(256+u)*30 + k];
    } else {
        if (k >= 30 && k < 158) v = gWhh[(256+u)*128 + (k-30)];
    }
    g_Wcat[idx] = v;
}

__global__ void pack_enc(const float* __restrict__ eWih, const float* __restrict__ eWhh,
                         const float* __restrict__ eb)
{
    int idx = blockIdx.x*blockDim.x + threadIdx.x;
    if (idx >= NSEG*512*128) return;
    int s  = idx / (512*128);
    int r2 = idx % (512*128);
    int pr = r2 / 128, k = r2 % 128;
    int orig = (pr&3)*128 + (pr>>2);
    g_eWih[idx] = eWih[(size_t)s*512*128 + orig*128 + k];
    g_eWhh[idx] = eWhh[(size_t)s*512*128 + orig*128 + k];
    if (k == 0) g_eb[s*512 + pr] = eb[s*512 + orig];
}

__global__ void pack_dec(const float* __restrict__ dWih, const float* __restrict__ dWhh,
                         const float* __restrict__ db)
{
    int idx = blockIdx.x*blockDim.x + threadIdx.x;
    if (idx >= 512*KQ) return;
    int pr = idx/KQ, k = idx%KQ;
    int orig = (pr&3)*128 + (pr>>2);
    g_dWih[idx] = dWih[orig*KQ + k];
    if (k < 128) g_dWhh[pr*128 + k] = dWhh[orig*128 + k];
    if (k == 0)  g_db[pr] = db[orig];
}

/* ------------------------------------------------------------------ */
/* tf32 GEMM, 128x128 tile, 256 thr (8 warps 2x4, warp tile 64x32)     */
/* aMode: 0=A[r*K+k]; 1=GRU concat [x|h|0] K=160; 2=query K=180        */
/* epi:   0=bias+store C (ldc=512); 1=GRU combine -> g_hv              */
/* ------------------------------------------------------------------ */
__global__ __launch_bounds__(256) void gemm_tf32(
    int aMode, int seg,
    const float* __restrict__ A, const float* __restrict__ ftf, int K,
    const float* __restrict__ W, const float* __restrict__ bias,
    float* __restrict__ C, int epi)
{
    __shared__ uint32_t As[16][132];
    __shared__ uint32_t Bs[16][132];
    __shared__ int4 rowinfo[128];

    int tid = threadIdx.x;
    int m0 = blockIdx.x*128;
    int n0 = blockIdx.y*128;
    int w = tid>>5, lane = tid&31;
    int wm = w>>2, wn = w&3;
    int g = lane>>2, tig = lane&3;
    int lk = tid & 15, lr = tid >> 4;

    if (aMode != 0 && tid < 128) {
        int r = m0 + tid;
        int b = r/SP, t = r - b*SP;
        rowinfo[tid] = make_int4((b*CTX + seg*SP + t)*30, r*NC, r*4, b*18);
    }
    if (aMode != 0) __syncthreads();

    float acc[4][4][4];
    #pragma unroll
    for (int i = 0; i < 4; i++)
        #pragma unroll
        for (int j = 0; j < 4; j++)
            #pragma unroll
            for (int q = 0; q < 4; q++) acc[i][j][q] = 0.0f;

    for (int k0 = 0; k0 < K; k0 += 16) {
        int k = k0 + lk;
        bool kv = (k < K);
        #pragma unroll
        for (int i = 0; i < 8; i++) {
            int m = lr + i*16;
            float v = 0.0f;
            if (kv) {
                if (aMode == 0) v = A[(size_t)(m0+m)*K + k];
                else {
                    int4 ri = rowinfo[m];
                    if (k < 30)       v = g_inputs[ri.x + k];
                    else if (k < 158) v = g_enc[(size_t)ri.y + (k-30)];
                    else if (aMode == 2) {
                        if (k < 162) v = ftf[ri.z + (k-158)];
                        else if (k < 180) v = g_static[ri.w + (k-162)];
                    }
                }
            }
            As[lk][m] = f2tf(v);
        }
        #pragma unroll
        for (int i = 0; i < 8; i++) {
            int n = lr + i*16;
            float v = kv ? W[(size_t)(n0+n)*K + k] : 0.0f;
            Bs[lk][n] = f2tf(v);
        }
        __syncthreads();
        #pragma unroll
        for (int ks = 0; ks < 2; ks++) {
            int k8 = ks*8;
            uint32_t a[4][4];
            #pragma unroll
            for (int mi = 0; mi < 4; mi++) {
                int mr = wm*64 + mi*16;
                a[mi][0] = As[k8+tig  ][mr+g];
                a[mi][1] = As[k8+tig  ][mr+g+8];
                a[mi][2] = As[k8+tig+4][mr+g];
                a[mi][3] = As[k8+tig+4][mr+g+8];
            }
            #pragma unroll
            for (int ni = 0; ni < 4; ni++) {
                int nb = wn*32 + ni*8;
                uint32_t bb[2];
                bb[0] = Bs[k8+tig  ][nb+g];
                bb[1] = Bs[k8+tig+4][nb+g];
                #pragma unroll
                for (int mi = 0; mi < 4; mi++)
                    mma8(acc[mi][ni], a[mi], bb);
            }
        }
        __syncthreads();
    }

    if (epi == 0) {
        #pragma unroll
        for (int mi = 0; mi < 4; mi++) {
            int row = m0 + wm*64 + mi*16 + g;
            #pragma unroll
            for (int ni = 0; ni < 4; ni++) {
                int col = n0 + wn*32 + ni*8 + 2*tig;
                float b0 = bias[col], b1 = bias[col+1];
                float2 v0 = make_float2(acc[mi][ni][0]+b0, acc[mi][ni][1]+b1);
                float2 v1 = make_float2(acc[mi][ni][2]+b0, acc[mi][ni][3]+b1);
                *(float2*)&C[(size_t)row*512 + col]     = v0;
                *(float2*)&C[(size_t)(row+8)*512 + col] = v1;
            }
        }
    } else {
        #pragma unroll
        for (int mi = 0; mi < 4; mi++) {
            int rowb = m0 + wm*64 + mi*16 + g;
            #pragma unroll
            for (int ni = 0; ni < 4; ni++) {
                int col = n0 + wn*32 + ni*8 + 2*tig;
                float b0 = bias[col], b1 = bias[col+1];
                float c0 = acc[mi][ni][0] + b0;
                float c1 = acc[mi][ni][1] + b1;
                float c2 = acc[mi][ni][2] + b0;
                float c3 = acc[mi][ni][3] + b1;
                float r0 = __shfl_xor_sync(0xffffffffu, c0, 1);
                float r1 = __shfl_xor_sync(0xffffffffu, c1, 1);
                float r2 = __shfl_xor_sync(0xffffffffu, c2, 1);
                float r3 = __shfl_xor_sync(0xffffffffu, c3, 1);
                int u = col >> 2;
                int row; float rg, zg, ing, hng;
                if ((tig & 1) == 0) { rg = c0; zg = c1; ing = r0; hng = r1; row = rowb; }
                else                { ing = c2; hng = c3; rg = r2; zg = r3; row = rowb+8; }
                float rr = sigm(rg), zz = sigm(zg);
                float nn = tanhf(ing + rr*hng);
                float hold = g_enc[(size_t)row*NC + u];
                g_hv[(size_t)row*NC + u] = (1.0f - zz)*nn + zz*hold;
            }
        }
    }
}

/* ------------------------------------------------------------------ */
/* tf32 LSTM step: 128 batch rows x 128 gate cols per block            */
/* ------------------------------------------------------------------ */
__global__ __launch_bounds__(256) void lstm_tf32(
    const float* __restrict__ Whh,   /* packed [512][128] */
    const float* __restrict__ xw,    /* [NROWS][512] packed, bias folded */
    const float* __restrict__ hin,
    float*       __restrict__ hout,
    float*       __restrict__ ys,
    int t)
{
    __shared__ uint32_t As[16][132];
    __shared__ uint32_t Bs[16][132];

    int tid = threadIdx.x;
    int b0 = blockIdx.x*128;
    int n0 = blockIdx.y*128;
    int w = tid>>5, lane = tid&31;
    int wm = w>>2, wn = w&3;
    int g = lane>>2, tig = lane&3;
    int lk = tid & 15, lr = tid >> 4;

    float acc[4][4][4];
    #pragma unroll
    for (int i = 0; i < 4; i++)
        #pragma unroll
        for (int j = 0; j < 4; j++)
            #pragma unroll
            for (int q = 0; q < 4; q++) acc[i][j][q] = 0.0f;

    for (int k0 = 0; k0 < 128; k0 += 16) {
        int k = k0 + lk;
        #pragma unroll
        for (int i = 0; i < 8; i++) {
            int m = lr + i*16;
            As[lk][m] = f2tf(hin[(size_t)(b0+m)*NC + k]);
        }
        #pragma unroll
        for (int i = 0; i < 8; i++) {
            int n = lr + i*16;
            Bs[lk][n] = f2tf(Whh[(size_t)(n0+n)*NC + k]);
        }
        __syncthreads();
        #pragma unroll
        for (int ks = 0; ks < 2; ks++) {
            int k8 = ks*8;
            uint32_t a[4][4];
            #pragma unroll
            for (int mi = 0; mi < 4; mi++) {
                int mr = wm*64 + mi*16;
                a[mi][0] = As[k8+tig  ][mr+g];
                a[mi][1] = As[k8+tig  ][mr+g+8];
                a[mi][2] = As[k8+tig+4][mr+g];
                a[mi][3] = As[k8+tig+4][mr+g+8];
            }
            #pragma unroll
            for (int ni = 0; ni < 4; ni++) {
                int nb = wn*32 + ni*8;
                uint32_t bb[2];
                bb[0] = Bs[k8+tig  ][nb+g];
                bb[1] = Bs[k8+tig+4][nb+g];
                #pragma unroll
                for (int mi = 0; mi < 4; mi++)
                    mma8(acc[mi][ni], a[mi], bb);
            }
        }
        __syncthreads();
    }

    #pragma unroll
    for (int mi = 0; mi < 4; mi++) {
        int rb = b0 + wm*64 + mi*16 + g;
        #pragma unroll
        for (int ni = 0; ni < 4; ni++) {
            int col = n0 + wn*32 + ni*8 + 2*tig;
            size_t x0 = ((size_t)rb*SP + t)*512 + col;
            size_t x1 = ((size_t)(rb+8)*SP + t)*512 + col;
            float c0 = acc[mi][ni][0] + xw[x0];
            float c1 = acc[mi][ni][1] + xw[x0+1];
            float c2 = acc[mi][ni][2] + xw[x1];
            float c3 = acc[mi][ni][3] + xw[x1+1];
            float r0 = __shfl_xor_sync(0xffffffffu, c0, 1);
            float r1 = __shfl_xor_sync(0xffffffffu, c1, 1);
            float r2 = __shfl_xor_sync(0xffffffffu, c2, 1);
            float r3 = __shfl_xor_sync(0xffffffffu, c3, 1);
            int u = col >> 2;
            int b; float ig, fg, gg, og;
            if ((tig & 1) == 0) { ig = c0; fg = c1; gg = r0; og = r1; b = rb; }
            else                { gg = c2; og = c3; ig = r2; fg = r3; b = rb+8; }
            float cold = g_c[b*NC + u];
            float cn = sigm(fg)*cold + sigm(ig)*tanhf(gg);
            float hn = sigm(og)*tanhf(cn);
            g_c[b*NC + u] = cn;
            hout[b*NC + u] = hn;
            ys[((size_t)b*SP + t)*NC + u] = hn;
        }
    }
}

/* ---------------- output projection + rescale ---------------------- */
__global__ void out_kernel(const float* __restrict__ oW,
                           const float* __restrict__ ob,
                           float* __restrict__ out)
{
    int r    = blockIdx.x*8 + (threadIdx.x >> 5);
    int lane = threadIdx.x & 31;
    float s = 0.0f;
    #pragma unroll
    for (int k = 0; k < 4; k++)
        s += g_dec[(size_t)r*NC + lane + 32*k]*oW[lane + 32*k];
    #pragma unroll
    for (int o = 16; o; o >>= 1) s += __shfl_down_sync(0xffffffffu, s, o);
    if (lane == 0)
        out[r] = (s + ob[0])*g_scale[r/SP];
}

/* ---------------- host driver -------------------------------------- */
extern "C" void kernel_launch(void* const* d_in, const int* in_sizes, int n_in,
                              void* d_out, int out_size)
{
    const int*   cat   = (const int*)  d_in[0];
    const float* sreal = (const float*)d_in[1];
    const float* ptf   = (const float*)d_in[2];
    const float* pt    = (const float*)d_in[3];
    const float* pov   = (const float*)d_in[4];
    const float* ftf   = (const float*)d_in[5];
    const float* emb   = (const float*)d_in[6];
    const float* gWih  = (const float*)d_in[7];
    const float* gWhh  = (const float*)d_in[8];
    const float* gbih  = (const float*)d_in[9];
    const float* gbhh  = (const float*)d_in[10];
    const float* eWih  = (const float*)d_in[11];
    const float* eWhh  = (const float*)d_in[12];
    const float* eb    = (const float*)d_in[13];
    const float* dWih  = (const float*)d_in[14];
    const float* dWhh  = (const float*)d_in[15];
    const float* db    = (const float*)d_in[16];
    const float* oW    = (const float*)d_in[17];
    const float* ob    = (const float*)d_in[18];
    float* out = (float*)d_out;

    float *p_hv, *p_xw, *p_enc, *p_dec, *p_h0, *p_h1;
    float *p_Wcat, *p_bcat, *p_eWih, *p_eWhh, *p_eb, *p_dWih, *p_dWhh, *p_db;
    cudaGetSymbolAddress((void**)&p_hv,   g_hv);
    cudaGetSymbolAddress((void**)&p_xw,   g_xw);
    cudaGetSymbolAddress((void**)&p_enc,  g_enc);
    cudaGetSymbolAddress((void**)&p_dec,  g_dec);
    cudaGetSymbolAddress((void**)&p_h0,   g_h0);
    cudaGetSymbolAddress((void**)&p_h1,   g_h1);
    cudaGetSymbolAddress((void**)&p_Wcat, g_Wcat);
    cudaGetSymbolAddress((void**)&p_bcat, g_bcat);
    cudaGetSymbolAddress((void**)&p_eWih, g_eWih);
    cudaGetSymbolAddress((void**)&p_eWhh, g_eWhh);
    cudaGetSymbolAddress((void**)&p_eb,   g_eb);
    cudaGetSymbolAddress((void**)&p_dWih, g_dWih);
    cudaGetSymbolAddress((void**)&p_dWhh, g_dWhh);
    cudaGetSymbolAddress((void**)&p_db,   g_db);
    float* hb[2] = {p_h0, p_h1};

    init_zero<<<(NROWS*NC + 255)/256, 256>>>();
    row_stats<<<BATCH/8, 256>>>(pt, pov);
    build_inputs<<<BATCH, 192>>>(cat, sreal, ptf, pt, emb);
    pack_gru<<<(512*KCAT + 255)/256, 256>>>(gWih, gWhh, gbih, gbhh);
    pack_enc<<<(NSEG*512*128 + 255)/256, 256>>>(eWih, eWhh, eb);
    pack_dec<<<(512*KQ + 255)/256, 256>>>(dWih, dWhh, db);

    dim3 gGrid(NROWS/128, 4), gThr(256);
    dim3 lGrid(BATCH/128, 4);

    for (int i = 0; i < NSEG; i++) {
        /* fused GRU: gates over concat[x|h], epilogue -> g_hv */
        gemm_tf32<<<gGrid, gThr>>>(1, i, nullptr, nullptr, KCAT,
                                   p_Wcat, p_bcat, nullptr, 1);
        /* xw = hv @ eWih_packed^T + eb  */
        gemm_tf32<<<gGrid, gThr>>>(0, 0, p_hv, nullptr, NC,
                                   p_eWih + (size_t)i*512*128,
                                   p_eb + i*512, p_xw, 0);
        for (int t = 0; t < SP; t++)
            lstm_tf32<<<lGrid, gThr>>>(p_eWhh + (size_t)i*512*128, p_xw,
                                       hb[t & 1], hb[(t & 1) ^ 1], p_enc, t);
    }

    /* decoder: xw = query @ dWih_packed^T + db (query assembled in A-stage) */
    gemm_tf32<<<gGrid, gThr>>>(2, 0, nullptr, ftf, KQ, p_dWih, p_db, p_xw, 0);
    for (int t = 0; t < SP; t++)
        lstm_tf32<<<lGrid, gThr>>>(p_dWhh, p_xw,
                                   hb[t & 1], hb[(t & 1) ^ 1], p_dec, t);

    out_kernel<<<NROWS/8, 256>>>(oW, ob, out);
}

// round 12
// speedup vs baseline: 1.4747x; 1.2801x over previous
#include <cuda_runtime.h>
#include <math.h>
#include <stdint.h>

#define BATCH 8192
#define CTX   168
#define SP    24
#define HIST  336
#define NC    128
#define NSEG  7
#define NROWS (BATCH*SP)
#define KCAT  160
#define KQ    180

/* scratch (device globals; allocation-free, replay-safe by construction) */
__device__ float g_inputs[BATCH*CTX*30];
__device__ float g_xw[(size_t)NROWS*512];
__device__ float g_hv[(size_t)NROWS*NC];
__device__ float g_enc[(size_t)NROWS*NC];
__device__ float g_dec[(size_t)NROWS*NC];
__device__ float g_h0[BATCH*NC];
__device__ float g_c[BATCH*NC];
__device__ float g_scale[BATCH];
__device__ float g_wsum[BATCH];
__device__ float g_wcnt[BATCH];
__device__ float g_static[BATCH*18];
__device__ float g_part[2048];
__device__ float g_tot[2];
/* packed weights: row = unit*4 + gate */
__device__ float g_Wcat[512*KCAT];
__device__ float g_bcat[512];
__device__ float g_eWih[NSEG*512*NC];
__device__ float g_eWhh[NSEG*512*NC];
__device__ float g_eb[NSEG*512];
__device__ float g_dWih[512*KQ];
__device__ float g_dWhh[512*NC];
__device__ float g_db[512];

__device__ __forceinline__ float sigm(float x){ return 1.0f/(1.0f+expf(-x)); }
__device__ __forceinline__ uint32_t f2tf(float x){
    uint32_t r; asm("cvt.rna.tf32.f32 %0, %1;" : "=r"(r) : "f"(x)); return r;
}
__device__ __forceinline__ void mma8(float* c, const uint32_t* a, const uint32_t* b){
    asm volatile("mma.sync.aligned.m16n8k8.row.col.f32.tf32.tf32.f32 "
        "{%0,%1,%2,%3}, {%4,%5,%6,%7}, {%8,%9}, {%0,%1,%2,%3};\n"
        : "+f"(c[0]),"+f"(c[1]),"+f"(c[2]),"+f"(c[3])
        : "r"(a[0]),"r"(a[1]),"r"(a[2]),"r"(a[3]), "r"(b[0]),"r"(b[1]));
}

/* ---------------- stats: per-row + deterministic per-block partials -- */
__global__ void row_stats(const float* __restrict__ pt,
                          const float* __restrict__ pov)
{
    __shared__ float pws[8], pwc[8];
    int w    = threadIdx.x >> 5;
    int b    = blockIdx.x*8 + w;
    int lane = threadIdx.x & 31;
    float ws = 0.0f, wc = 0.0f;
    for (int t = lane; t < CTX; t += 32) {
        float wv = pov[b*HIST + CTX + t];
        float d  = pt [b*HIST + CTX + t];
        ws += fabsf(d)*wv;  wc += wv;
    }
    #pragma unroll
    for (int o = 16; o; o >>= 1) {
        ws += __shfl_down_sync(0xffffffffu, ws, o);
        wc += __shfl_down_sync(0xffffffffu, wc, o);
    }
    if (lane == 0) {
        g_wsum[b] = ws;  g_wcnt[b] = wc;
        pws[w] = ws;  pwc[w] = wc;
    }
    __syncthreads();
    if (threadIdx.x == 0) {
        float a = 0.0f, c = 0.0f;
        #pragma unroll
        for (int i = 0; i < 8; i++) { a += pws[i]; c += pwc[i]; }
        g_part[2*blockIdx.x]   = a;
        g_part[2*blockIdx.x+1] = c;
    }
}

/* ---------------- pack GRU weights + reduce totals (block 0) -------- */
__global__ void pack_gru(const float* __restrict__ gWih, const float* __restrict__ gWhh,
                         const float* __restrict__ gbih, const float* __restrict__ gbhh)
{
    if (blockIdx.x == 0) {
        __shared__ float r0[256], r1[256];
        int tid = threadIdx.x;
        float s0 = 0.0f, s1 = 0.0f;
        for (int i = tid; i < 1024; i += 256) {
            s0 += g_part[2*i];  s1 += g_part[2*i+1];
        }
        r0[tid] = s0;  r1[tid] = s1;
        __syncthreads();
        for (int o = 128; o; o >>= 1) {
            if (tid < o) { r0[tid] += r0[tid+o]; r1[tid] += r1[tid+o]; }
            __syncthreads();
        }
        if (tid == 0) { g_tot[0] = r0[0];  g_tot[1] = r1[0]; }
    }
    int idx = blockIdx.x*blockDim.x + threadIdx.x;
    if (idx < 512) {
        int u = idx>>2, gg = idx&3;  float bv;
        if      (gg == 0) bv = gbih[u]     + gbhh[u];
        else if (gg == 1) bv = gbih[128+u] + gbhh[128+u];
        else if (gg == 2) bv = gbih[256+u];
        else              bv = gbhh[256+u];
        g_bcat[idx] = bv;
    }
    if (idx >= 512*KCAT) return;
    int pr = idx/KCAT, k = idx%KCAT;
    int u = pr>>2, gg = pr&3;
    float v = 0.0f;
    if (gg == 0) {
        if (k < 30)       v = gWih[u*30 + k];
        else if (k < 158) v = gWhh[u*128 + (k-30)];
    } else if (gg == 1) {
        if (k < 30)       v = gWih[(128+u)*30 + k];
        else if (k < 158) v = gWhh[(128+u)*128 + (k-30)];
    } else if (gg == 2) {
        if (k < 30)       v = gWih[(256+u)*30 + k];
    } else {
        if (k >= 30 && k < 158) v = gWhh[(256+u)*128 + (k-30)];
    }
    g_Wcat[idx] = v;
}

/* ---------------- scale + static features + input tensor ----------- */
__global__ void build_inputs(const int*   __restrict__ cat,
                             const float* __restrict__ sreal,
                             const float* __restrict__ ptf,
                             const float* __restrict__ pt,
                             const float* __restrict__ emb)
{
    int b = blockIdx.x;
    __shared__ float s_scale;
    __shared__ float s_static[18];
    if (threadIdx.x == 0) {
        float ws  = g_wsum[b], wc = g_wcnt[b];
        float def = g_tot[0] / fmaxf(g_tot[1], 1.0f);
        float sc  = ws / fmaxf(wc, 1.0f);
        sc = (ws > 0.0f) ? sc : def;
        sc = fmaxf(1e-10f, sc);
        s_scale = sc;  g_scale[b] = sc;
    }
    __syncthreads();
    if (threadIdx.x < 18) {
        int c = threadIdx.x;  float v;
        if (c < 16)       v = emb[cat[b]*16 + c];
        else if (c == 16) v = sreal[b];
        else              v = logf(s_scale);
        s_static[c] = v;  g_static[b*18 + c] = v;
    }
    __syncthreads();
    float inv = 1.0f / s_scale;
    const int lagv[8] = {24,48,72,96,120,144,168,0};
    for (int t = threadIdx.x; t < CTX; t += blockDim.x) {
        float* o = &g_inputs[(b*CTX + t)*30];
        #pragma unroll
        for (int l = 0; l < 8; l++)
            o[l] = pt[b*HIST + (CTX - lagv[l]) + t]*inv;
        #pragma unroll
        for (int f = 0; f < 4; f++)
            o[8+f] = ptf[(b*HIST + CTX + t)*4 + f];
        #pragma unroll
        for (int c = 0; c < 18; c++)
            o[12+c] = s_static[c];
    }
}

/* ---------------- pack encoder / decoder weights -------------------- */
__global__ void pack_enc(const float* __restrict__ eWih, const float* __restrict__ eWhh,
                         const float* __restrict__ eb)
{
    int idx = blockIdx.x*blockDim.x + threadIdx.x;
    if (idx >= NSEG*512*128) return;
    int s  = idx / (512*128);
    int r2 = idx % (512*128);
    int pr = r2 / 128, k = r2 % 128;
    int orig = (pr&3)*128 + (pr>>2);
    g_eWih[idx] = eWih[(size_t)s*512*128 + orig*128 + k];
    g_eWhh[idx] = eWhh[(size_t)s*512*128 + orig*128 + k];
    if (k == 0) g_eb[s*512 + pr] = eb[s*512 + orig];
}

__global__ void pack_dec(const float* __restrict__ dWih, const float* __restrict__ dWhh,
                         const float* __restrict__ db)
{
    int idx = blockIdx.x*blockDim.x + threadIdx.x;
    if (idx >= 512*KQ) return;
    int pr = idx/KQ, k = idx%KQ;
    int orig = (pr&3)*128 + (pr>>2);
    g_dWih[idx] = dWih[orig*KQ + k];
    if (k < 128) g_dWhh[pr*128 + k] = dWhh[orig*128 + k];
    if (k == 0)  g_db[pr] = db[orig];
}

/* ------------------------------------------------------------------ */
/* tf32 GEMM, 128x128 tile, 256 thr (8 warps 2x4, warp tile 64x32)     */
/* aMode: 0=A[r*ldw+k]; 1=GRU concat [x|h|0] ; 2=query                 */
/* epi:   0=bias+store C (ldc=512); 1=GRU combine -> g_hv              */
/* zeroH: seg0 GRU, treat h as zero (no g_enc reads)                   */
/* ------------------------------------------------------------------ */
__global__ __launch_bounds__(256) void gemm_tf32(
    int aMode, int seg,
    const float* __restrict__ A, const float* __restrict__ ftf,
    int K, int ldw,
    const float* __restrict__ W, const float* __restrict__ bias,
    float* __restrict__ C, int epi, int zeroH)
{
    __shared__ uint32_t As[16][132];
    __shared__ uint32_t Bs[16][132];
    __shared__ int4 rowinfo[128];

    int tid = threadIdx.x;
    int m0 = blockIdx.x*128;
    int n0 = blockIdx.y*128;
    int w = tid>>5, lane = tid&31;
    int wm = w>>2, wn = w&3;
    int g = lane>>2, tig = lane&3;
    int lk = tid & 15, lr = tid >> 4;

    if (aMode != 0 && tid < 128) {
        int r = m0 + tid;
        int b = r/SP, t = r - b*SP;
        rowinfo[tid] = make_int4((b*CTX + seg*SP + t)*30, r*NC, r*4, b*18);
    }
    if (aMode != 0) __syncthreads();

    float acc[4][4][4];
    #pragma unroll
    for (int i = 0; i < 4; i++)
        #pragma unroll
        for (int j = 0; j < 4; j++)
            #pragma unroll
            for (int q = 0; q < 4; q++) acc[i][j][q] = 0.0f;

    for (int k0 = 0; k0 < K; k0 += 16) {
        int k = k0 + lk;
        bool kv = (k < K);
        #pragma unroll
        for (int i = 0; i < 8; i++) {
            int m = lr + i*16;
            float v = 0.0f;
            if (kv) {
                if (aMode == 0) v = A[(size_t)(m0+m)*ldw + k];
                else {
                    int4 ri = rowinfo[m];
                    if (k < 30)                 v = g_inputs[ri.x + k];
                    else if (!zeroH && k < 158) v = g_enc[(size_t)ri.y + (k-30)];
                    else if (aMode == 2) {
                        if (k >= 158 && k < 162)      v = ftf[ri.z + (k-158)];
                        else if (k >= 162 && k < 180) v = g_static[ri.w + (k-162)];
                    }
                }
            }
            As[lk][m] = f2tf(v);
        }
        #pragma unroll
        for (int i = 0; i < 8; i++) {
            int n = lr + i*16;
            float v = kv ? W[(size_t)(n0+n)*ldw + k] : 0.0f;
            Bs[lk][n] = f2tf(v);
        }
        __syncthreads();
        #pragma unroll
        for (int ks = 0; ks < 2; ks++) {
            int k8 = ks*8;
            uint32_t a[4][4];
            #pragma unroll
            for (int mi = 0; mi < 4; mi++) {
                int mr = wm*64 + mi*16;
                a[mi][0] = As[k8+tig  ][mr+g];
                a[mi][1] = As[k8+tig  ][mr+g+8];
                a[mi][2] = As[k8+tig+4][mr+g];
                a[mi][3] = As[k8+tig+4][mr+g+8];
            }
            #pragma unroll
            for (int ni = 0; ni < 4; ni++) {
                int nb = wn*32 + ni*8;
                uint32_t bb[2];
                bb[0] = Bs[k8+tig  ][nb+g];
                bb[1] = Bs[k8+tig+4][nb+g];
                #pragma unroll
                for (int mi = 0; mi < 4; mi++)
                    mma8(acc[mi][ni], a[mi], bb);
            }
        }
        __syncthreads();
    }

    if (epi == 0) {
        #pragma unroll
        for (int mi = 0; mi < 4; mi++) {
            int row = m0 + wm*64 + mi*16 + g;
            #pragma unroll
            for (int ni = 0; ni < 4; ni++) {
                int col = n0 + wn*32 + ni*8 + 2*tig;
                float b0 = bias[col], b1 = bias[col+1];
                float2 v0 = make_float2(acc[mi][ni][0]+b0, acc[mi][ni][1]+b1);
                float2 v1 = make_float2(acc[mi][ni][2]+b0, acc[mi][ni][3]+b1);
                *(float2*)&C[(size_t)row*512 + col]     = v0;
                *(float2*)&C[(size_t)(row+8)*512 + col] = v1;
            }
        }
    } else {
        #pragma unroll
        for (int mi = 0; mi < 4; mi++) {
            int rowb = m0 + wm*64 + mi*16 + g;
            #pragma unroll
            for (int ni = 0; ni < 4; ni++) {
                int col = n0 + wn*32 + ni*8 + 2*tig;
                float b0 = bias[col], b1 = bias[col+1];
                float c0 = acc[mi][ni][0] + b0;
                float c1 = acc[mi][ni][1] + b1;
                float c2 = acc[mi][ni][2] + b0;
                float c3 = acc[mi][ni][3] + b1;
                float r0 = __shfl_xor_sync(0xffffffffu, c0, 1);
                float r1 = __shfl_xor_sync(0xffffffffu, c1, 1);
                float r2 = __shfl_xor_sync(0xffffffffu, c2, 1);
                float r3 = __shfl_xor_sync(0xffffffffu, c3, 1);
                int u = col >> 2;
                int row; float rg, zg, ing, hng;
                if ((tig & 1) == 0) { rg = c0; zg = c1; ing = r0; hng = r1; row = rowb; }
                else                { ing = c2; hng = c3; rg = r2; zg = r3; row = rowb+8; }
                float rr = sigm(rg), zz = sigm(zg);
                float nn = tanhf(ing + rr*hng);
                float hold = zeroH ? 0.0f : g_enc[(size_t)row*NC + u];
                g_hv[(size_t)row*NC + u] = (1.0f - zz)*nn + zz*hold;
            }
        }
    }
}

/* ------------------------------------------------------------------ */
/* fused tf32 LSTM sequence: ONE kernel runs all 24 steps.             */
/* block = 32 batch rows (independent recurrence), 256 thr, 8 warps    */
/* warp tile 32x64 (wn = warp id).  h in smem (tf32), c in registers.  */
/* ------------------------------------------------------------------ */
__global__ __launch_bounds__(256) void lstm_seq(
    const float* __restrict__ Whh,   /* packed [512][128] */
    const float* __restrict__ xw,    /* [NROWS][512] packed, bias folded */
    float*       __restrict__ ys,    /* [NROWS][128] */
    int initHC)
{
    __shared__ uint32_t Bs[8][520];
    __shared__ uint32_t sh_h[32][132];

    int tid = threadIdx.x;
    int b0 = blockIdx.x*32;
    int w = tid>>5, lane = tid&31;
    int g = lane>>2, tig = lane&3;
    int wn = w;                      /* 0..7 col group of 64 gates */

    /* load / init h (tf32 in smem) */
    for (int i = tid; i < 32*128; i += 256) {
        int m = i >> 7, k = i & 127;
        float hv = initHC ? 0.0f : g_h0[(b0+m)*NC + k];
        sh_h[m][k] = f2tf(hv);
    }
    /* load / init c (registers, fixed ownership) */
    float c_reg[16];
    #pragma unroll
    for (int mi = 0; mi < 2; mi++)
        #pragma unroll
        for (int ni = 0; ni < 8; ni++) {
            int rowl = mi*16 + g + ((tig & 1) ? 8 : 0);
            int u    = (wn*64 + ni*8 + 2*tig) >> 2;
            c_reg[mi*8+ni] = initHC ? 0.0f : g_c[(b0+rowl)*NC + u];
        }
    __syncthreads();

    for (int t = 0; t < SP; t++) {
        float acc[2][8][4];
        #pragma unroll
        for (int i = 0; i < 2; i++)
            #pragma unroll
            for (int j = 0; j < 8; j++)
                #pragma unroll
                for (int q = 0; q < 4; q++) acc[i][j][q] = 0.0f;

        for (int k0 = 0; k0 < 128; k0 += 8) {
            /* stage Whh chunk: thread covers rows n = tid, tid+256 */
            #pragma unroll
            for (int hh = 0; hh < 2; hh++) {
                int n = tid + hh*256;
                const float4* src = (const float4*)&Whh[(size_t)n*NC + k0];
                float4 v0 = src[0], v1 = src[1];
                Bs[0][n] = f2tf(v0.x);  Bs[1][n] = f2tf(v0.y);
                Bs[2][n] = f2tf(v0.z);  Bs[3][n] = f2tf(v0.w);
                Bs[4][n] = f2tf(v1.x);  Bs[5][n] = f2tf(v1.y);
                Bs[6][n] = f2tf(v1.z);  Bs[7][n] = f2tf(v1.w);
            }
            __syncthreads();

            uint32_t a[2][4];
            #pragma unroll
            for (int mi = 0; mi < 2; mi++) {
                int mr = mi*16;
                a[mi][0] = sh_h[mr+g  ][k0+tig  ];
                a[mi][1] = sh_h[mr+g+8][k0+tig  ];
                a[mi][2] = sh_h[mr+g  ][k0+tig+4];
                a[mi][3] = sh_h[mr+g+8][k0+tig+4];
            }
            #pragma unroll
            for (int ni = 0; ni < 8; ni++) {
                int nb = wn*64 + ni*8;
                uint32_t bb[2];
                bb[0] = Bs[tig  ][nb+g];
                bb[1] = Bs[tig+4][nb+g];
                #pragma unroll
                for (int mi = 0; mi < 2; mi++)
                    mma8(acc[mi][ni], a[mi], bb);
            }
            __syncthreads();
        }

        /* epilogue: add xw, exchange gates, cell update */
        #pragma unroll
        for (int mi = 0; mi < 2; mi++) {
            int rbl = mi*16 + g;                 /* local row */
            #pragma unroll
            for (int ni = 0; ni < 8; ni++) {
                int col = wn*64 + ni*8 + 2*tig;
                size_t x0 = ((size_t)(b0+rbl  )*SP + t)*512 + col;
                size_t x1 = ((size_t)(b0+rbl+8)*SP + t)*512 + col;
                float c0 = acc[mi][ni][0] + xw[x0];
                float c1 = acc[mi][ni][1] + xw[x0+1];
                float c2 = acc[mi][ni][2] + xw[x1];
                float c3 = acc[mi][ni][3] + xw[x1+1];
                float r0 = __shfl_xor_sync(0xffffffffu, c0, 1);
                float r1 = __shfl_xor_sync(0xffffffffu, c1, 1);
                float r2 = __shfl_xor_sync(0xffffffffu, c2, 1);
                float r3 = __shfl_xor_sync(0xffffffffu, c3, 1);
                int u = col >> 2;
                int rowl; float ig, fg, gg, og;
                if ((tig & 1) == 0) { ig = c0; fg = c1; gg = r0; og = r1; rowl = rbl; }
                else                { gg = c2; og = c3; ig = r2; fg = r3; rowl = rbl+8; }
                float cold = c_reg[mi*8+ni];
                float cn = sigm(fg)*cold + sigm(ig)*tanhf(gg);
                float hn = sigm(og)*tanhf(cn);
                c_reg[mi*8+ni] = cn;
                sh_h[rowl][u] = f2tf(hn);
                ys[((size_t)(b0+rowl)*SP + t)*NC + u] = hn;
            }
        }
        __syncthreads();
    }

    /* persist h (tf32-rounded is exact for all downstream uses) and c */
    for (int i = tid; i < 32*128; i += 256) {
        int m = i >> 7, k = i & 127;
        g_h0[(b0+m)*NC + k] = __uint_as_float(sh_h[m][k]);
    }
    #pragma unroll
    for (int mi = 0; mi < 2; mi++)
        #pragma unroll
        for (int ni = 0; ni < 8; ni++) {
            int rowl = mi*16 + g + ((tig & 1) ? 8 : 0);
            int u    = (wn*64 + ni*8 + 2*tig) >> 2;
            g_c[(b0+rowl)*NC + u] = c_reg[mi*8+ni];
        }
}

/* ---------------- output projection + rescale ---------------------- */
__global__ void out_kernel(const float* __restrict__ oW,
                           const float* __restrict__ ob,
                           float* __restrict__ out)
{
    int r    = blockIdx.x*8 + (threadIdx.x >> 5);
    int lane = threadIdx.x & 31;
    float s = 0.0f;
    #pragma unroll
    for (int k = 0; k < 4; k++)
        s += g_dec[(size_t)r*NC + lane + 32*k]*oW[lane + 32*k];
    #pragma unroll
    for (int o = 16; o; o >>= 1) s += __shfl_down_sync(0xffffffffu, s, o);
    if (lane == 0)
        out[r] = (s + ob[0])*g_scale[r/SP];
}

/* ---------------- host driver -------------------------------------- */
extern "C" void kernel_launch(void* const* d_in, const int* in_sizes, int n_in,
                              void* d_out, int out_size)
{
    const int*   cat   = (const int*)  d_in[0];
    const float* sreal = (const float*)d_in[1];
    const float* ptf   = (const float*)d_in[2];
    const float* pt    = (const float*)d_in[3];
    const float* pov   = (const float*)d_in[4];
    const float* ftf   = (const float*)d_in[5];
    const float* emb   = (const float*)d_in[6];
    const float* gWih  = (const float*)d_in[7];
    const float* gWhh  = (const float*)d_in[8];
    const float* gbih  = (const float*)d_in[9];
    const float* gbhh  = (const float*)d_in[10];
    const float* eWih  = (const float*)d_in[11];
    const float* eWhh  = (const float*)d_in[12];
    const float* eb    = (const float*)d_in[13];
    const float* dWih  = (const float*)d_in[14];
    const float* dWhh  = (const float*)d_in[15];
    const float* db    = (const float*)d_in[16];
    const float* oW    = (const float*)d_in[17];
    const float* ob    = (const float*)d_in[18];
    float* out = (float*)d_out;

    float *p_hv, *p_xw, *p_enc, *p_dec;
    float *p_Wcat, *p_bcat, *p_eWih, *p_eWhh, *p_eb, *p_dWih, *p_dWhh, *p_db;
    cudaGetSymbolAddress((void**)&p_hv,   g_hv);
    cudaGetSymbolAddress((void**)&p_xw,   g_xw);
    cudaGetSymbolAddress((void**)&p_enc,  g_enc);
    cudaGetSymbolAddress((void**)&p_dec,  g_dec);
    cudaGetSymbolAddress((void**)&p_Wcat, g_Wcat);
    cudaGetSymbolAddress((void**)&p_bcat, g_bcat);
    cudaGetSymbolAddress((void**)&p_eWih, g_eWih);
    cudaGetSymbolAddress((void**)&p_eWhh, g_eWhh);
    cudaGetSymbolAddress((void**)&p_eb,   g_eb);
    cudaGetSymbolAddress((void**)&p_dWih, g_dWih);
    cudaGetSymbolAddress((void**)&p_dWhh, g_dWhh);
    cudaGetSymbolAddress((void**)&p_db,   g_db);

    dim3 gGrid(NROWS/128, 4), gThr(256);

    /* 1 */ row_stats<<<BATCH/8, 256>>>(pt, pov);
    /* 2 */ pack_gru<<<(512*KCAT + 255)/256, 256>>>(gWih, gWhh, gbih, gbhh);
    /* 3 */ build_inputs<<<BATCH, 192>>>(cat, sreal, ptf, pt, emb);
    /* 4: GRU seg0 (h==0 -> K loop truncated to 32) — ncu capture slot */
    gemm_tf32<<<gGrid, gThr>>>(1, 0, nullptr, nullptr, 32, KCAT,
                               p_Wcat, p_bcat, nullptr, 1, 1);
    /* 5,6 */
    pack_enc<<<(NSEG*512*128 + 255)/256, 256>>>(eWih, eWhh, eb);
    pack_dec<<<(512*KQ + 255)/256, 256>>>(dWih, dWhh, db);

    /* seg 0 LSTM */
    gemm_tf32<<<gGrid, gThr>>>(0, 0, p_hv, nullptr, NC, NC,
                               p_eWih, p_eb, p_xw, 0, 0);
    lstm_seq<<<BATCH/32, 256>>>(p_eWhh, p_xw, p_enc, 1);

    for (int i = 1; i < NSEG; i++) {
        gemm_tf32<<<gGrid, gThr>>>(1, i, nullptr, nullptr, KCAT, KCAT,
                                   p_Wcat, p_bcat, nullptr, 1, 0);
        gemm_tf32<<<gGrid, gThr>>>(0, 0, p_hv, nullptr, NC, NC,
                                   p_eWih + (size_t)i*512*128,
                                   p_eb + i*512, p_xw, 0, 0);
        lstm_seq<<<BATCH/32, 256>>>(p_eWhh + (size_t)i*512*128, p_xw, p_enc, 0);
    }

    /* decoder */
    gemm_tf32<<<gGrid, gThr>>>(2, 0, nullptr, ftf, KQ, KQ,
                               p_dWih, p_db, p_xw, 0, 0);
    lstm_seq<<<BATCH/32, 256>>>(p_dWhh, p_xw, p_dec, 0);

    out_kernel<<<NROWS/8, 256>>>(oW, ob, out);
}

// round 13
// speedup vs baseline: 2.1947x; 1.4882x over previous
#include <cuda_runtime.h>
#include <math.h>
#include <stdint.h>

#define BATCH 8192
#define CTX   168
#define SP    24
#define HIST  336
#define NC    128
#define NSEG  7
#define NROWS (BATCH*SP)
#define KCAT  160     /* [h 128 | x 30 | pad 2] */
#define KQP   192     /* [h 128 | x 32 | ftf 4 | st 18 | pad 10] */

/* scratch (device globals; allocation-free, replay-safe) */
__device__ float g_inputs[BATCH*CTX*32];      /* padded to 32, tf32-rounded */
__device__ float g_xw[(size_t)NROWS*512];
__device__ float g_hv[(size_t)NROWS*NC];      /* tf32-rounded */
__device__ float g_enc[(size_t)NROWS*NC];     /* tf32-rounded */
__device__ float g_dec[(size_t)NROWS*NC];
__device__ float g_h0[BATCH*NC];
__device__ float g_c[BATCH*NC];
__device__ float g_scale[BATCH];
__device__ float g_wsum[BATCH];
__device__ float g_wcnt[BATCH];
__device__ float g_static[BATCH*18];          /* tf32-rounded */
__device__ float g_part[2048];
__device__ float g_tot[2];
/* packed weights, tf32-rounded bits; row = unit*4 + gate */
__device__ float g_Wcat[512*KCAT];
__device__ float g_bcat[512];
__device__ float g_eWih[NSEG*512*NC];
__device__ float g_eWhh[NSEG*512*NC];
__device__ float g_eb[NSEG*512];
__device__ float g_dWih[512*KQP];
__device__ float g_dWhh[512*NC];
__device__ float g_db[512];

__device__ __forceinline__ float sigm(float x){ return 1.0f/(1.0f+expf(-x)); }
__device__ __forceinline__ uint32_t f2tf(float x){
    uint32_t r; asm("cvt.rna.tf32.f32 %0, %1;" : "=r"(r) : "f"(x)); return r;
}
__device__ __forceinline__ float tfr(float x){ return __uint_as_float(f2tf(x)); }
__device__ __forceinline__ void mma8(float* c, const uint32_t* a, const uint32_t* b){
    asm volatile("mma.sync.aligned.m16n8k8.row.col.f32.tf32.tf32.f32 "
        "{%0,%1,%2,%3}, {%4,%5,%6,%7}, {%8,%9}, {%0,%1,%2,%3};\n"
        : "+f"(c[0]),"+f"(c[1]),"+f"(c[2]),"+f"(c[3])
        : "r"(a[0]),"r"(a[1]),"r"(a[2]),"r"(a[3]), "r"(b[0]),"r"(b[1]));
}

/* ---------------- stats ---------------- */
__global__ void row_stats(const float* __restrict__ pt,
                          const float* __restrict__ pov)
{
    __shared__ float pws[8], pwc[8];
    int w    = threadIdx.x >> 5;
    int b    = blockIdx.x*8 + w;
    int lane = threadIdx.x & 31;
    float ws = 0.0f, wc = 0.0f;
    for (int t = lane; t < CTX; t += 32) {
        float wv = pov[b*HIST + CTX + t];
        float d  = pt [b*HIST + CTX + t];
        ws += fabsf(d)*wv;  wc += wv;
    }
    #pragma unroll
    for (int o = 16; o; o >>= 1) {
        ws += __shfl_down_sync(0xffffffffu, ws, o);
        wc += __shfl_down_sync(0xffffffffu, wc, o);
    }
    if (lane == 0) {
        g_wsum[b] = ws;  g_wcnt[b] = wc;
        pws[w] = ws;  pwc[w] = wc;
    }
    __syncthreads();
    if (threadIdx.x == 0) {
        float a = 0.0f, c = 0.0f;
        #pragma unroll
        for (int i = 0; i < 8; i++) { a += pws[i]; c += pwc[i]; }
        g_part[2*blockIdx.x]   = a;
        g_part[2*blockIdx.x+1] = c;
    }
}

/* ---------------- pack GRU weights (layout [h128|x30|00]) + totals --- */
__global__ void pack_gru(const float* __restrict__ gWih, const float* __restrict__ gWhh,
                         const float* __restrict__ gbih, const float* __restrict__ gbhh)
{
    if (blockIdx.x == 0) {
        __shared__ float r0[256], r1[256];
        int tid = threadIdx.x;
        float s0 = 0.0f, s1 = 0.0f;
        for (int i = tid; i < 1024; i += 256) {
            s0 += g_part[2*i];  s1 += g_part[2*i+1];
        }
        r0[tid] = s0;  r1[tid] = s1;
        __syncthreads();
        for (int o = 128; o; o >>= 1) {
            if (tid < o) { r0[tid] += r0[tid+o]; r1[tid] += r1[tid+o]; }
            __syncthreads();
        }
        if (tid == 0) { g_tot[0] = r0[0];  g_tot[1] = r1[0]; }
    }
    int idx = blockIdx.x*blockDim.x + threadIdx.x;
    if (idx < 512) {
        int u = idx>>2, gg = idx&3;  float bv;
        if      (gg == 0) bv = gbih[u]     + gbhh[u];
        else if (gg == 1) bv = gbih[128+u] + gbhh[128+u];
        else if (gg == 2) bv = gbih[256+u];
        else              bv = gbhh[256+u];
        g_bcat[idx] = bv;
    }
    if (idx >= 512*KCAT) return;
    int pr = idx/KCAT, k = idx%KCAT;
    int u = pr>>2, gg = pr&3;
    float v = 0.0f;
    if (k < 128) {                       /* h-part */
        if      (gg == 0) v = gWhh[u*128 + k];
        else if (gg == 1) v = gWhh[(128+u)*128 + k];
        else if (gg == 3) v = gWhh[(256+u)*128 + k];
    } else if (k < 158) {                /* x-part */
        int xk = k - 128;
        if      (gg == 0) v = gWih[u*30 + xk];
        else if (gg == 1) v = gWih[(128+u)*30 + xk];
        else if (gg == 2) v = gWih[(256+u)*30 + xk];
    }
    g_Wcat[idx] = tfr(v);
}

/* ---------------- scale + static + input tensor (tf32-rounded) ------ */
__global__ void build_inputs(const int*   __restrict__ cat,
                             const float* __restrict__ sreal,
                             const float* __restrict__ ptf,
                             const float* __restrict__ pt,
                             const float* __restrict__ emb)
{
    int b = blockIdx.x;
    __shared__ float s_scale;
    __shared__ float s_static[18];
    if (threadIdx.x == 0) {
        float ws  = g_wsum[b], wc = g_wcnt[b];
        float def = g_tot[0] / fmaxf(g_tot[1], 1.0f);
        float sc  = ws / fmaxf(wc, 1.0f);
        sc = (ws > 0.0f) ? sc : def;
        sc = fmaxf(1e-10f, sc);
        s_scale = sc;  g_scale[b] = sc;
    }
    __syncthreads();
    if (threadIdx.x < 18) {
        int c = threadIdx.x;  float v;
        if (c < 16)       v = emb[cat[b]*16 + c];
        else if (c == 16) v = sreal[b];
        else              v = logf(s_scale);
        v = tfr(v);
        s_static[c] = v;  g_static[b*18 + c] = v;
    }
    __syncthreads();
    float inv = 1.0f / s_scale;
    const int lagv[8] = {24,48,72,96,120,144,168,0};
    for (int t = threadIdx.x; t < CTX; t += blockDim.x) {
        float* o = &g_inputs[(b*CTX + t)*32];
        #pragma unroll
        for (int l = 0; l < 8; l++)
            o[l] = tfr(pt[b*HIST + (CTX - lagv[l]) + t]*inv);
        #pragma unroll
        for (int f = 0; f < 4; f++)
            o[8+f] = tfr(ptf[(b*HIST + CTX + t)*4 + f]);
        #pragma unroll
        for (int c = 0; c < 18; c++)
            o[12+c] = s_static[c];
        o[30] = 0.0f;  o[31] = 0.0f;
    }
}

/* ---------------- pack encoder / decoder weights (tf32) -------------- */
__global__ void pack_enc(const float* __restrict__ eWih, const float* __restrict__ eWhh,
                         const float* __restrict__ eb)
{
    int idx = blockIdx.x*blockDim.x + threadIdx.x;
    if (idx >= NSEG*512*128) return;
    int s  = idx / (512*128);
    int r2 = idx % (512*128);
    int pr = r2 / 128, k = r2 % 128;
    int orig = (pr&3)*128 + (pr>>2);
    g_eWih[idx] = tfr(eWih[(size_t)s*512*128 + orig*128 + k]);
    g_eWhh[idx] = tfr(eWhh[(size_t)s*512*128 + orig*128 + k]);
    if (k == 0) g_eb[s*512 + pr] = eb[s*512 + orig];
}

/* decoder query layout: [enc128 | x32 | ftf4 | st18 | pad10] = 192 */
__global__ void pack_dec(const float* __restrict__ dWih, const float* __restrict__ dWhh,
                         const float* __restrict__ db)
{
    int idx = blockIdx.x*blockDim.x + threadIdx.x;
    if (idx >= 512*KQP) return;
    int pr = idx/KQP, k = idx%KQP;
    int orig = (pr&3)*128 + (pr>>2);
    float v = 0.0f;
    if (k < 128)       v = dWih[orig*180 + 30 + k];
    else if (k < 158)  v = dWih[orig*180 + (k-128)];
    else if (k < 160)  v = 0.0f;
    else if (k < 164)  v = dWih[orig*180 + 158 + (k-160)];
    else if (k < 182)  v = dWih[orig*180 + 162 + (k-164)];
    g_dWih[idx] = tfr(v);
    if (k < 128) g_dWhh[pr*128 + k] = tfr(dWhh[orig*128 + k]);
    if (k == 0)  g_db[pr] = db[orig];
}

/* ------------------------------------------------------------------ */
/* tf32 GEMM, 128x128 tile, BK=32, 256 thr (8 warps 2x4, wtile 64x32)  */
/* aMode: 0=A[r*ldw+k]; 1=GRU [h|x]; 2=query [h|x|ftf|st]; 3=x-only    */
/* epi:   0=bias+store C (ldc=512); 1=GRU combine -> g_hv              */
/* ------------------------------------------------------------------ */
__global__ __launch_bounds__(256,2) void gemm_tf32(
    int aMode, int seg,
    const float* __restrict__ A, const float* __restrict__ ftf,
    int K, int ldw,
    const float* __restrict__ W, const float* __restrict__ bias,
    float* __restrict__ C, int epi, int zeroH)
{
    __shared__ float As[128][36];
    __shared__ float Bs[128][36];
    __shared__ int4 rowinfo[128];

    int tid = threadIdx.x;
    int m0 = blockIdx.x*128;
    int n0 = blockIdx.y*128;
    int w = tid>>5, lane = tid&31;
    int wm = w>>2, wn = w&3;
    int g = lane>>2, tig = lane&3;
    int srow = tid >> 3;          /* 0..31 */
    int sq   = tid & 7;           /* 0..7  */

    if (aMode != 0 && tid < 128) {
        int r = m0 + tid;
        int b = r/SP, t = r - b*SP;
        rowinfo[tid] = make_int4((b*CTX + seg*SP + t)*32, r*NC, r*4, b*18);
    }
    if (aMode != 0) __syncthreads();

    float acc[4][4][4];
    #pragma unroll
    for (int i = 0; i < 4; i++)
        #pragma unroll
        for (int j = 0; j < 4; j++)
            #pragma unroll
            for (int q = 0; q < 4; q++) acc[i][j][q] = 0.0f;

    for (int k0 = 0; k0 < K; k0 += 32) {
        int kq = k0 + sq*4;
        /* stage A: 4 rows per thread, fully coalesced float4 */
        #pragma unroll
        for (int j = 0; j < 4; j++) {
            int m = srow + j*32;
            float4 v;
            if (aMode == 0) {
                v = *(const float4*)(A + (size_t)(m0+m)*ldw + kq);
            } else if (aMode == 3) {
                v = *(const float4*)(g_inputs + rowinfo[m].x + kq);
            } else {
                int4 ri = rowinfo[m];
                if (kq < 128)       v = *(const float4*)(g_enc + (size_t)ri.y + kq);
                else if (kq < 160)  v = *(const float4*)(g_inputs + ri.x + (kq-128));
                else {
                    float e[4];
                    #pragma unroll
                    for (int q = 0; q < 4; q++) {
                        int kk = kq + q;  float x = 0.0f;
                        if (kk < 164)       x = tfr(ftf[ri.z + (kk-160)]);
                        else if (kk < 182)  x = g_static[ri.w + (kk-164)];
                        e[q] = x;
                    }
                    v = make_float4(e[0], e[1], e[2], e[3]);
                }
            }
            *(float4*)&As[m][sq*4] = v;
        }
        /* stage B (weights pre-tf32) */
        #pragma unroll
        for (int j = 0; j < 4; j++) {
            int n = srow + j*32;
            float4 v = *(const float4*)(W + (size_t)(n0+n)*ldw + kq);
            *(float4*)&Bs[n][sq*4] = v;
        }
        __syncthreads();
        #pragma unroll
        for (int ks = 0; ks < 4; ks++) {
            int k8 = ks*8;
            uint32_t a[4][4];
            #pragma unroll
            for (int mi = 0; mi < 4; mi++) {
                int mr = wm*64 + mi*16;
                a[mi][0] = __float_as_uint(As[mr+g  ][k8+tig  ]);
                a[mi][1] = __float_as_uint(As[mr+g+8][k8+tig  ]);
                a[mi][2] = __float_as_uint(As[mr+g  ][k8+tig+4]);
                a[mi][3] = __float_as_uint(As[mr+g+8][k8+tig+4]);
            }
            #pragma unroll
            for (int ni = 0; ni < 4; ni++) {
                int nb = wn*32 + ni*8;
                uint32_t bb[2];
                bb[0] = __float_as_uint(Bs[nb+g][k8+tig  ]);
                bb[1] = __float_as_uint(Bs[nb+g][k8+tig+4]);
                #pragma unroll
                for (int mi = 0; mi < 4; mi++)
                    mma8(acc[mi][ni], a[mi], bb);
            }
        }
        __syncthreads();
    }

    if (epi == 0) {
        #pragma unroll
        for (int mi = 0; mi < 4; mi++) {
            int row = m0 + wm*64 + mi*16 + g;
            #pragma unroll
            for (int ni = 0; ni < 4; ni++) {
                int col = n0 + wn*32 + ni*8 + 2*tig;
                float b0 = bias[col], b1 = bias[col+1];
                float2 v0 = make_float2(acc[mi][ni][0]+b0, acc[mi][ni][1]+b1);
                float2 v1 = make_float2(acc[mi][ni][2]+b0, acc[mi][ni][3]+b1);
                *(float2*)&C[(size_t)row*512 + col]     = v0;
                *(float2*)&C[(size_t)(row+8)*512 + col] = v1;
            }
        }
    } else {
        #pragma unroll
        for (int mi = 0; mi < 4; mi++) {
            int rowb = m0 + wm*64 + mi*16 + g;
            #pragma unroll
            for (int ni = 0; ni < 4; ni++) {
                int col = n0 + wn*32 + ni*8 + 2*tig;
                float b0 = bias[col], b1 = bias[col+1];
                float c0 = acc[mi][ni][0] + b0;
                float c1 = acc[mi][ni][1] + b1;
                float c2 = acc[mi][ni][2] + b0;
                float c3 = acc[mi][ni][3] + b1;
                float r0 = __shfl_xor_sync(0xffffffffu, c0, 1);
                float r1 = __shfl_xor_sync(0xffffffffu, c1, 1);
                float r2 = __shfl_xor_sync(0xffffffffu, c2, 1);
                float r3 = __shfl_xor_sync(0xffffffffu, c3, 1);
                int u = col >> 2;
                int row; float rg, zg, ing, hng;
                if ((tig & 1) == 0) { rg = c0; zg = c1; ing = r0; hng = r1; row = rowb; }
                else                { ing = c2; hng = c3; rg = r2; zg = r3; row = rowb+8; }
                float rr = sigm(rg), zz = sigm(zg);
                float nn = tanhf(ing + rr*hng);
                float hold = zeroH ? 0.0f : g_enc[(size_t)row*NC + u];
                g_hv[(size_t)row*NC + u] = tfr((1.0f - zz)*nn + zz*hold);
            }
        }
    }
}

/* ------------------------------------------------------------------ */
/* fused tf32 LSTM sequence: ONE kernel runs all 24 steps.             */
/* ------------------------------------------------------------------ */
__global__ __launch_bounds__(256) void lstm_seq(
    const float* __restrict__ Whh,   /* packed [512][128], tf32 bits */
    const float* __restrict__ xw,
    float*       __restrict__ ys,
    int initHC, int roundYs)
{
    __shared__ uint32_t Bs[8][520];
    __shared__ uint32_t sh_h[32][132];

    int tid = threadIdx.x;
    int b0 = blockIdx.x*32;
    int w = tid>>5, lane = tid&31;
    int g = lane>>2, tig = lane&3;
    int wn = w;

    for (int i = tid; i < 32*128; i += 256) {
        int m = i >> 7, k = i & 127;
        float hv = initHC ? 0.0f : g_h0[(b0+m)*NC + k];
        sh_h[m][k] = f2tf(hv);
    }
    float c_reg[16];
    #pragma unroll
    for (int mi = 0; mi < 2; mi++)
        #pragma unroll
        for (int ni = 0; ni < 8; ni++) {
            int rowl = mi*16 + g + ((tig & 1) ? 8 : 0);
            int u    = (wn*64 + ni*8 + 2*tig) >> 2;
            c_reg[mi*8+ni] = initHC ? 0.0f : g_c[(b0+rowl)*NC + u];
        }
    __syncthreads();

    for (int t = 0; t < SP; t++) {
        float acc[2][8][4];
        #pragma unroll
        for (int i = 0; i < 2; i++)
            #pragma unroll
            for (int j = 0; j < 8; j++)
                #pragma unroll
                for (int q = 0; q < 4; q++) acc[i][j][q] = 0.0f;

        for (int k0 = 0; k0 < 128; k0 += 8) {
            #pragma unroll
            for (int hh = 0; hh < 2; hh++) {
                int n = tid + hh*256;
                const float4* src = (const float4*)&Whh[(size_t)n*NC + k0];
                float4 v0 = src[0], v1 = src[1];
                Bs[0][n] = __float_as_uint(v0.x);  Bs[1][n] = __float_as_uint(v0.y);
                Bs[2][n] = __float_as_uint(v0.z);  Bs[3][n] = __float_as_uint(v0.w);
                Bs[4][n] = __float_as_uint(v1.x);  Bs[5][n] = __float_as_uint(v1.y);
                Bs[6][n] = __float_as_uint(v1.z);  Bs[7][n] = __float_as_uint(v1.w);
            }
            __syncthreads();

            uint32_t a[2][4];
            #pragma unroll
            for (int mi = 0; mi < 2; mi++) {
                int mr = mi*16;
                a[mi][0] = sh_h[mr+g  ][k0+tig  ];
                a[mi][1] = sh_h[mr+g+8][k0+tig  ];
                a[mi][2] = sh_h[mr+g  ][k0+tig+4];
                a[mi][3] = sh_h[mr+g+8][k0+tig+4];
            }
            #pragma unroll
            for (int ni = 0; ni < 8; ni++) {
                int nb = wn*64 + ni*8;
                uint32_t bb[2];
                bb[0] = Bs[tig  ][nb+g];
                bb[1] = Bs[tig+4][nb+g];
                #pragma unroll
                for (int mi = 0; mi < 2; mi++)
                    mma8(acc[mi][ni], a[mi], bb);
            }
            __syncthreads();
        }

        #pragma unroll
        for (int mi = 0; mi < 2; mi++) {
            int rbl = mi*16 + g;
            #pragma unroll
            for (int ni = 0; ni < 8; ni++) {
                int col = wn*64 + ni*8 + 2*tig;
                size_t x0 = ((size_t)(b0+rbl  )*SP + t)*512 + col;
                size_t x1 = ((size_t)(b0+rbl+8)*SP + t)*512 + col;
                float c0 = acc[mi][ni][0] + xw[x0];
                float c1 = acc[mi][ni][1] + xw[x0+1];
                float c2 = acc[mi][ni][2] + xw[x1];
                float c3 = acc[mi][ni][3] + xw[x1+1];
                float r0 = __shfl_xor_sync(0xffffffffu, c0, 1);
                float r1 = __shfl_xor_sync(0xffffffffu, c1, 1);
                float r2 = __shfl_xor_sync(0xffffffffu, c2, 1);
                float r3 = __shfl_xor_sync(0xffffffffu, c3, 1);
                int u = col >> 2;
                int rowl; float ig, fg, gg, og;
                if ((tig & 1) == 0) { ig = c0; fg = c1; gg = r0; og = r1; rowl = rbl; }
                else                { gg = c2; og = c3; ig = r2; fg = r3; rowl = rbl+8; }
                float cold = c_reg[mi*8+ni];
                float cn = sigm(fg)*cold + sigm(ig)*tanhf(gg);
                float hn = sigm(og)*tanhf(cn);
                c_reg[mi*8+ni] = cn;
                uint32_t hb = f2tf(hn);
                sh_h[rowl][u] = hb;
                ys[((size_t)(b0+rowl)*SP + t)*NC + u] =
                    roundYs ? __uint_as_float(hb) : hn;
            }
        }
        __syncthreads();
    }

    for (int i = tid; i < 32*128; i += 256) {
        int m = i >> 7, k = i & 127;
        g_h0[(b0+m)*NC + k] = __uint_as_float(sh_h[m][k]);
    }
    #pragma unroll
    for (int mi = 0; mi < 2; mi++)
        #pragma unroll
        for (int ni = 0; ni < 8; ni++) {
            int rowl = mi*16 + g + ((tig & 1) ? 8 : 0);
            int u    = (wn*64 + ni*8 + 2*tig) >> 2;
            g_c[(b0+rowl)*NC + u] = c_reg[mi*8+ni];
        }
}

/* ---------------- output projection + rescale ---------------------- */
__global__ void out_kernel(const float* __restrict__ oW,
                           const float* __restrict__ ob,
                           float* __restrict__ out)
{
    int r    = blockIdx.x*8 + (threadIdx.x >> 5);
    int lane = threadIdx.x & 31;
    float s = 0.0f;
    #pragma unroll
    for (int k = 0; k < 4; k++)
        s += g_dec[(size_t)r*NC + lane + 32*k]*oW[lane + 32*k];
    #pragma unroll
    for (int o = 16; o; o >>= 1) s += __shfl_down_sync(0xffffffffu, s, o);
    if (lane == 0)
        out[r] = (s + ob[0])*g_scale[r/SP];
}

/* ---------------- host driver -------------------------------------- */
extern "C" void kernel_launch(void* const* d_in, const int* in_sizes, int n_in,
                              void* d_out, int out_size)
{
    const int*   cat   = (const int*)  d_in[0];
    const float* sreal = (const float*)d_in[1];
    const float* ptf   = (const float*)d_in[2];
    const float* pt    = (const float*)d_in[3];
    const float* pov   = (const float*)d_in[4];
    const float* ftf   = (const float*)d_in[5];
    const float* emb   = (const float*)d_in[6];
    const float* gWih  = (const float*)d_in[7];
    const float* gWhh  = (const float*)d_in[8];
    const float* gbih  = (const float*)d_in[9];
    const float* gbhh  = (const float*)d_in[10];
    const float* eWih  = (const float*)d_in[11];
    const float* eWhh  = (const float*)d_in[12];
    const float* eb    = (const float*)d_in[13];
    const float* dWih  = (const float*)d_in[14];
    const float* dWhh  = (const float*)d_in[15];
    const float* db    = (const float*)d_in[16];
    const float* oW    = (const float*)d_in[17];
    const float* ob    = (const float*)d_in[18];
    float* out = (float*)d_out;

    float *p_hv, *p_xw, *p_enc, *p_dec;
    float *p_Wcat, *p_bcat, *p_eWih, *p_eWhh, *p_eb, *p_dWih, *p_dWhh, *p_db;
    cudaGetSymbolAddress((void**)&p_hv,   g_hv);
    cudaGetSymbolAddress((void**)&p_xw,   g_xw);
    cudaGetSymbolAddress((void**)&p_enc,  g_enc);
    cudaGetSymbolAddress((void**)&p_dec,  g_dec);
    cudaGetSymbolAddress((void**)&p_Wcat, g_Wcat);
    cudaGetSymbolAddress((void**)&p_bcat, g_bcat);
    cudaGetSymbolAddress((void**)&p_eWih, g_eWih);
    cudaGetSymbolAddress((void**)&p_eWhh, g_eWhh);
    cudaGetSymbolAddress((void**)&p_eb,   g_eb);
    cudaGetSymbolAddress((void**)&p_dWih, g_dWih);
    cudaGetSymbolAddress((void**)&p_dWhh, g_dWhh);
    cudaGetSymbolAddress((void**)&p_db,   g_db);

    dim3 gGrid(NROWS/128, 4), gThr(256);

    /* 1 */ row_stats<<<BATCH/8, 256>>>(pt, pov);
    /* 2 */ pack_gru<<<(512*KCAT + 255)/256, 256>>>(gWih, gWhh, gbih, gbhh);
    /* 3 */ build_inputs<<<BATCH, 192>>>(cat, sreal, ptf, pt, emb);
    /* 4: GRU seg0, x-only (W offset +128), K=32 — ncu capture slot */
    gemm_tf32<<<gGrid, gThr>>>(3, 0, nullptr, nullptr, 32, KCAT,
                               p_Wcat + 128, p_bcat, nullptr, 1, 1);
    /* 5,6 */
    pack_enc<<<(NSEG*512*128 + 255)/256, 256>>>(eWih, eWhh, eb);
    pack_dec<<<(512*KQP + 255)/256, 256>>>(dWih, dWhh, db);

    /* seg 0 LSTM */
    gemm_tf32<<<gGrid, gThr>>>(0, 0, p_hv, nullptr, NC, NC,
                               p_eWih, p_eb, p_xw, 0, 0);
    lstm_seq<<<BATCH/32, 256>>>(p_eWhh, p_xw, p_enc, 1, 1);

    for (int i = 1; i < NSEG; i++) {
        gemm_tf32<<<gGrid, gThr>>>(1, i, nullptr, nullptr, KCAT, KCAT,
                                   p_Wcat, p_bcat, nullptr, 1, 0);
        gemm_tf32<<<gGrid, gThr>>>(0, 0, p_hv, nullptr, NC, NC,
                                   p_eWih + (size_t)i*512*128,
                                   p_eb + i*512, p_xw, 0, 0);
        lstm_seq<<<BATCH/32, 256>>>(p_eWhh + (size_t)i*512*128, p_xw, p_enc, 0, 1);
    }

    /* decoder: query = [enc|x|ftf|static] assembled in A-stage, K=192 */
    gemm_tf32<<<gGrid, gThr>>>(2, 0, nullptr, ftf, KQP, KQP,
                               p_dWih, p_db, p_xw, 0, 0);
    lstm_seq<<<BATCH/32, 256>>>(p_dWhh, p_xw, p_dec, 0, 0);

    out_kernel<<<NROWS/8, 256>>>(oW, ob, out);
}

// round 14
// speedup vs baseline: 4.2135x; 1.9198x over previous
#include <cuda_runtime.h>
#include <cuda_fp16.h>
#include <math.h>
#include <stdint.h>

#define BATCH 8192
#define CTX   168
#define SP    24
#define HIST  336
#define NC    128
#define NSEG  7
#define NROWS (BATCH*SP)
#define KCAT  160     /* [h 128 | x 30 | pad 2] */
#define KQP   192     /* [h 128 | x 32 | extra 32] */

/* scratch (device globals; allocation-free, replay-safe) */
__device__ __align__(16) __half g_inputs[BATCH*CTX*32];
__device__ __align__(16) __half g_extra[(size_t)NROWS*32];
__device__ float  g_xw[(size_t)NROWS*512];
__device__ __align__(16) __half g_hv[(size_t)NROWS*NC];
__device__ __align__(16) __half g_enc[(size_t)NROWS*NC];
__device__ float  g_dec[(size_t)NROWS*NC];
__device__ float  g_h0[BATCH*NC];
__device__ float  g_c[BATCH*NC];
__device__ float  g_scale[BATCH];
__device__ float  g_wsum[BATCH];
__device__ float  g_wcnt[BATCH];
__device__ float  g_static[BATCH*18];
__device__ float  g_part[2048];
__device__ float  g_tot[2];
/* packed weights, fp16; row = unit*4 + gate */
__device__ __align__(16) __half g_Wcat[512*KCAT];
__device__ float  g_bcat[512];
__device__ __align__(16) __half g_eWih[NSEG*512*NC];
__device__ __align__(16) __half g_eWhh[NSEG*512*NC];
__device__ float  g_eb[NSEG*512];
__device__ __align__(16) __half g_dWih[512*KQP];
__device__ __align__(16) __half g_dWhh[512*NC];
__device__ float  g_db[512];

__device__ __forceinline__ float sigm(float x){ return 1.0f/(1.0f+expf(-x)); }

__device__ __forceinline__ void ldsm4(uint32_t* r, uint32_t sa){
    asm volatile("ldmatrix.sync.aligned.m8n8.x4.shared.b16 {%0,%1,%2,%3}, [%4];"
        : "=r"(r[0]),"=r"(r[1]),"=r"(r[2]),"=r"(r[3]) : "r"(sa));
}
__device__ __forceinline__ void mma16(float* c, const uint32_t* a, uint32_t b0, uint32_t b1){
    asm volatile("mma.sync.aligned.m16n8k16.row.col.f32.f16.f16.f32 "
        "{%0,%1,%2,%3}, {%4,%5,%6,%7}, {%8,%9}, {%0,%1,%2,%3};\n"
        : "+f"(c[0]),"+f"(c[1]),"+f"(c[2]),"+f"(c[3])
        : "r"(a[0]),"r"(a[1]),"r"(a[2]),"r"(a[3]), "r"(b0),"r"(b1));
}

/* ---------------- stats ---------------- */
__global__ void row_stats(const float* __restrict__ pt,
                          const float* __restrict__ pov)
{
    __shared__ float pws[8], pwc[8];
    int w    = threadIdx.x >> 5;
    int b    = blockIdx.x*8 + w;
    int lane = threadIdx.x & 31;
    float ws = 0.0f, wc = 0.0f;
    for (int t = lane; t < CTX; t += 32) {
        float wv = pov[b*HIST + CTX + t];
        float d  = pt [b*HIST + CTX + t];
        ws += fabsf(d)*wv;  wc += wv;
    }
    #pragma unroll
    for (int o = 16; o; o >>= 1) {
        ws += __shfl_down_sync(0xffffffffu, ws, o);
        wc += __shfl_down_sync(0xffffffffu, wc, o);
    }
    if (lane == 0) {
        g_wsum[b] = ws;  g_wcnt[b] = wc;
        pws[w] = ws;  pwc[w] = wc;
    }
    __syncthreads();
    if (threadIdx.x == 0) {
        float a = 0.0f, c = 0.0f;
        #pragma unroll
        for (int i = 0; i < 8; i++) { a += pws[i]; c += pwc[i]; }
        g_part[2*blockIdx.x]   = a;
        g_part[2*blockIdx.x+1] = c;
    }
}

/* ---------------- pack GRU weights [h128|x30|00] + totals ----------- */
__global__ void pack_gru(const float* __restrict__ gWih, const float* __restrict__ gWhh,
                         const float* __restrict__ gbih, const float* __restrict__ gbhh)
{
    if (blockIdx.x == 0) {
        __shared__ float r0[256], r1[256];
        int tid = threadIdx.x;
        float s0 = 0.0f, s1 = 0.0f;
        for (int i = tid; i < 1024; i += 256) {
            s0 += g_part[2*i];  s1 += g_part[2*i+1];
        }
        r0[tid] = s0;  r1[tid] = s1;
        __syncthreads();
        for (int o = 128; o; o >>= 1) {
            if (tid < o) { r0[tid] += r0[tid+o]; r1[tid] += r1[tid+o]; }
            __syncthreads();
        }
        if (tid == 0) { g_tot[0] = r0[0];  g_tot[1] = r1[0]; }
    }
    int idx = blockIdx.x*blockDim.x + threadIdx.x;
    if (idx < 512) {
        int u = idx>>2, gg = idx&3;  float bv;
        if      (gg == 0) bv = gbih[u]     + gbhh[u];
        else if (gg == 1) bv = gbih[128+u] + gbhh[128+u];
        else if (gg == 2) bv = gbih[256+u];
        else              bv = gbhh[256+u];
        g_bcat[idx] = bv;
    }
    if (idx >= 512*KCAT) return;
    int pr = idx/KCAT, k = idx%KCAT;
    int u = pr>>2, gg = pr&3;
    float v = 0.0f;
    if (k < 128) {
        if      (gg == 0) v = gWhh[u*128 + k];
        else if (gg == 1) v = gWhh[(128+u)*128 + k];
        else if (gg == 3) v = gWhh[(256+u)*128 + k];
    } else if (k < 158) {
        int xk = k - 128;
        if      (gg == 0) v = gWih[u*30 + xk];
        else if (gg == 1) v = gWih[(128+u)*30 + xk];
        else if (gg == 2) v = gWih[(256+u)*30 + xk];
    }
    g_Wcat[idx] = __float2half(v);
}

/* ---------------- scale + static + input tensor (fp16) -------------- */
__global__ void build_inputs(const int*   __restrict__ cat,
                             const float* __restrict__ sreal,
                             const float* __restrict__ ptf,
                             const float* __restrict__ pt,
                             const float* __restrict__ emb)
{
    int b = blockIdx.x;
    __shared__ float s_scale;
    __shared__ float s_static[18];
    if (threadIdx.x == 0) {
        float ws  = g_wsum[b], wc = g_wcnt[b];
        float def = g_tot[0] / fmaxf(g_tot[1], 1.0f);
        float sc  = ws / fmaxf(wc, 1.0f);
        sc = (ws > 0.0f) ? sc : def;
        sc = fmaxf(1e-10f, sc);
        s_scale = sc;  g_scale[b] = sc;
    }
    __syncthreads();
    if (threadIdx.x < 18) {
        int c = threadIdx.x;  float v;
        if (c < 16)       v = emb[cat[b]*16 + c];
        else if (c == 16) v = sreal[b];
        else              v = logf(s_scale);
        s_static[c] = v;  g_static[b*18 + c] = v;
    }
    __syncthreads();
    float inv = 1.0f / s_scale;
    const int lagv[8] = {24,48,72,96,120,144,168,0};
    for (int t = threadIdx.x; t < CTX; t += blockDim.x) {
        __half* o = &g_inputs[(b*CTX + t)*32];
        #pragma unroll
        for (int l = 0; l < 8; l++)
            o[l] = __float2half(pt[b*HIST + (CTX - lagv[l]) + t]*inv);
        #pragma unroll
        for (int f = 0; f < 4; f++)
            o[8+f] = __float2half(ptf[(b*HIST + CTX + t)*4 + f]);
        #pragma unroll
        for (int c = 0; c < 18; c++)
            o[12+c] = __float2half(s_static[c]);
        o[30] = __float2half(0.0f);  o[31] = __float2half(0.0f);
    }
}

/* ---------------- decoder extras: [ftf4|static18|pad10] ------------- */
__global__ void build_extra(const float* __restrict__ ftf)
{
    int r = blockIdx.x*blockDim.x + threadIdx.x;
    if (r >= NROWS) return;
    int b = r/SP;
    __half* e = &g_extra[(size_t)r*32];
    #pragma unroll
    for (int q = 0; q < 4; q++)  e[q] = __float2half(ftf[r*4 + q]);
    #pragma unroll
    for (int c = 0; c < 18; c++) e[4+c] = __float2half(g_static[b*18 + c]);
    #pragma unroll
    for (int c = 22; c < 32; c++) e[c] = __float2half(0.0f);
}

/* ---------------- pack encoder / decoder weights (fp16) -------------- */
__global__ void pack_enc(const float* __restrict__ eWih, const float* __restrict__ eWhh,
                         const float* __restrict__ eb)
{
    int idx = blockIdx.x*blockDim.x + threadIdx.x;
    if (idx >= NSEG*512*128) return;
    int s  = idx / (512*128);
    int r2 = idx % (512*128);
    int pr = r2 / 128, k = r2 % 128;
    int orig = (pr&3)*128 + (pr>>2);
    g_eWih[idx] = __float2half(eWih[(size_t)s*512*128 + orig*128 + k]);
    g_eWhh[idx] = __float2half(eWhh[(size_t)s*512*128 + orig*128 + k]);
    if (k == 0) g_eb[s*512 + pr] = eb[s*512 + orig];
}

__global__ void pack_dec(const float* __restrict__ dWih, const float* __restrict__ dWhh,
                         const float* __restrict__ db)
{
    int idx = blockIdx.x*blockDim.x + threadIdx.x;
    if (idx >= 512*KQP) return;
    int pr = idx/KQP, k = idx%KQP;
    int orig = (pr&3)*128 + (pr>>2);
    float v = 0.0f;
    if (k < 128)       v = dWih[orig*180 + 30 + k];
    else if (k < 158)  v = dWih[orig*180 + (k-128)];
    else if (k < 160)  v = 0.0f;
    else if (k < 164)  v = dWih[orig*180 + 158 + (k-160)];
    else if (k < 182)  v = dWih[orig*180 + 162 + (k-164)];
    g_dWih[idx] = __float2half(v);
    if (k < 128) g_dWhh[pr*128 + k] = __float2half(dWhh[orig*128 + k]);
    if (k == 0)  g_db[pr] = db[orig];
}

/* ------------------------------------------------------------------ */
/* fp16 GEMM, 128x128 tile, BK=32, 256 thr, ldmatrix + m16n8k16        */
/* aMode: 0=A[r*ldw+k]; 1=GRU [h|x]; 2=query [h|x|extra]; 3=x-only     */
/* epi:   0=bias+store C fp32 (ldc=512); 1=GRU combine -> g_hv (half)  */
/* smem rows padded to 40 halves (80B) for conflict-free LDSM          */
/* ------------------------------------------------------------------ */
__global__ __launch_bounds__(256,2) void gemm_fp16(
    int aMode, int seg,
    const __half* __restrict__ A, int K, int ldw,
    const __half* __restrict__ W, const float* __restrict__ bias,
    float* __restrict__ C, int epi, int zeroH)
{
    __shared__ __align__(16) __half Asm[128*40];
    __shared__ __align__(16) __half Bsm[128*40];
    __shared__ int4 rowinfo[128];

    int tid = threadIdx.x;
    int m0 = blockIdx.x*128, n0 = blockIdx.y*128;
    int w = tid>>5, lane = tid&31;
    int wm = w>>2, wn = w&3;
    int g = lane>>2, tig = lane&3;

    if (aMode != 0 && tid < 128) {
        int r = m0 + tid;
        int b = r/SP, t = r - b*SP;
        rowinfo[tid] = make_int4((b*CTX + seg*SP + t)*32, r*NC, r*32, 0);
    }

    /* LDSM addresses (constant across k0 iterations) */
    uint32_t aAddr[4], bAddr[2];
    {
        int rl = lane&15, ch = lane>>4;
        #pragma unroll
        for (int mi = 0; mi < 4; mi++) {
            int r = wm*64 + mi*16 + rl;
            aAddr[mi] = (uint32_t)__cvta_generic_to_shared(Asm + r*40 + ch*8);
        }
        int rb0 = (lane&7) + ((lane&16)>>1);
        int cb  = (lane>>3)&1;
        #pragma unroll
        for (int nig = 0; nig < 2; nig++) {
            int r = wn*32 + nig*16 + rb0;
            bAddr[nig] = (uint32_t)__cvta_generic_to_shared(Bsm + r*40 + cb*8);
        }
    }

    float acc[4][4][4];
    #pragma unroll
    for (int i = 0; i < 4; i++)
        #pragma unroll
        for (int j = 0; j < 4; j++)
            #pragma unroll
            for (int q = 0; q < 4; q++) acc[i][j][q] = 0.0f;

    int srow = tid>>2, scc = tid&3;
    if (aMode != 0) __syncthreads();

    for (int k0 = 0; k0 < K; k0 += 32) {
        int k = k0 + scc*8;
        #pragma unroll
        for (int j = 0; j < 2; j++) {
            int row = srow + j*64;
            const __half* src;
            if (aMode == 0)       src = A + (size_t)(m0+row)*ldw + k;
            else {
                int4 ri = rowinfo[row];
                if (aMode == 3)     src = g_inputs + ri.x + k;
                else if (k < 128)   src = g_enc + (size_t)ri.y + k;
                else if (k < 160)   src = g_inputs + ri.x + (k-128);
                else                src = g_extra + (size_t)ri.z + (k-160);
            }
            *(int4*)(Asm + row*40 + scc*8) = *(const int4*)src;
            *(int4*)(Bsm + row*40 + scc*8) = *(const int4*)(W + (size_t)(n0+row)*ldw + k);
        }
        __syncthreads();
        #pragma unroll
        for (int kk = 0; kk < 2; kk++) {
            uint32_t a[4][4];
            #pragma unroll
            for (int mi = 0; mi < 4; mi++) ldsm4(a[mi], aAddr[mi] + kk*32);
            #pragma unroll
            for (int nig = 0; nig < 2; nig++) {
                uint32_t bb[4];
                ldsm4(bb, bAddr[nig] + kk*32);
                #pragma unroll
                for (int mi = 0; mi < 4; mi++) {
                    mma16(acc[mi][nig*2],   a[mi], bb[0], bb[1]);
                    mma16(acc[mi][nig*2+1], a[mi], bb[2], bb[3]);
                }
            }
        }
        __syncthreads();
    }

    if (epi == 0) {
        #pragma unroll
        for (int mi = 0; mi < 4; mi++) {
            int row = m0 + wm*64 + mi*16 + g;
            #pragma unroll
            for (int ni = 0; ni < 4; ni++) {
                int col = n0 + wn*32 + ni*8 + 2*tig;
                float b0 = bias[col], b1 = bias[col+1];
                float2 v0 = make_float2(acc[mi][ni][0]+b0, acc[mi][ni][1]+b1);
                float2 v1 = make_float2(acc[mi][ni][2]+b0, acc[mi][ni][3]+b1);
                *(float2*)&C[(size_t)row*512 + col]     = v0;
                *(float2*)&C[(size_t)(row+8)*512 + col] = v1;
            }
        }
    } else {
        #pragma unroll
        for (int mi = 0; mi < 4; mi++) {
            int rowb = m0 + wm*64 + mi*16 + g;
            #pragma unroll
            for (int ni = 0; ni < 4; ni++) {
                int col = n0 + wn*32 + ni*8 + 2*tig;
                float b0 = bias[col], b1 = bias[col+1];
                float c0 = acc[mi][ni][0] + b0;
                float c1 = acc[mi][ni][1] + b1;
                float c2 = acc[mi][ni][2] + b0;
                float c3 = acc[mi][ni][3] + b1;
                float r0 = __shfl_xor_sync(0xffffffffu, c0, 1);
                float r1 = __shfl_xor_sync(0xffffffffu, c1, 1);
                float r2 = __shfl_xor_sync(0xffffffffu, c2, 1);
                float r3 = __shfl_xor_sync(0xffffffffu, c3, 1);
                int u = col >> 2;
                int row; float rg, zg, ing, hng;
                if ((tig & 1) == 0) { rg = c0; zg = c1; ing = r0; hng = r1; row = rowb; }
                else                { ing = c2; hng = c3; rg = r2; zg = r3; row = rowb+8; }
                float rr = sigm(rg), zz = sigm(zg);
                float nn = tanhf(ing + rr*hng);
                float hold = zeroH ? 0.0f : __half2float(g_enc[(size_t)row*NC + u]);
                g_hv[(size_t)row*NC + u] = __float2half((1.0f - zz)*nn + zz*hold);
            }
        }
    }
}

/* ------------------------------------------------------------------ */
/* fused fp16 LSTM sequence: ONE kernel, 24 steps, 64 rows/block,      */
/* 512 thr (16 warps 2x8, warp tile 32x64). h swizzled fp16 in smem.   */
/* ------------------------------------------------------------------ */
__global__ __launch_bounds__(512) void lstm_seq(
    const __half* __restrict__ Whh,   /* packed [512][128] */
    const float*  __restrict__ xw,    /* [NROWS][512], bias folded */
    void*         __restrict__ ysv,
    int initHC, int ysHalf)
{
    __shared__ __align__(16) __half Bs[512*24];   /* 48B rows */
    __shared__ __align__(16) __half Hs[64*128];   /* 256B rows, swizzled */

    int tid = threadIdx.x;
    int b0 = blockIdx.x*64;
    int w = tid>>5, lane = tid&31;
    int wm = w>>3, wn = w&7;
    int g = lane>>2, tig = lane&3;

    for (int i = tid; i < 64*128; i += 512) {
        int m = i>>7, k = i&127;
        float hv = initHC ? 0.0f : g_h0[(b0+m)*NC + k];
        Hs[m*128 + (((k>>3) ^ (m&7))<<3) + (k&7)] = __float2half(hv);
    }
    float c_reg[16];
    #pragma unroll
    for (int mi = 0; mi < 2; mi++)
        #pragma unroll
        for (int ni = 0; ni < 8; ni++) {
            int rowl = wm*32 + mi*16 + g + ((tig & 1) ? 8 : 0);
            int u    = (wn*64 + ni*8 + 2*tig) >> 2;
            c_reg[mi*8+ni] = initHC ? 0.0f : g_c[(b0+rowl)*NC + u];
        }

    /* LDSM address bases */
    uint32_t hBase[2]; int hS[2]; int hCh = lane>>4;
    {
        int rl = lane&15;
        #pragma unroll
        for (int mi = 0; mi < 2; mi++) {
            int r = wm*32 + mi*16 + rl;
            hBase[mi] = (uint32_t)__cvta_generic_to_shared(Hs + r*128);
            hS[mi] = r & 7;
        }
    }
    uint32_t bAddr[4];
    {
        int rb0 = (lane&7) + ((lane&16)>>1);
        int cb  = (lane>>3)&1;
        #pragma unroll
        for (int nig = 0; nig < 4; nig++) {
            int r = wn*64 + nig*16 + rb0;
            bAddr[nig] = (uint32_t)__cvta_generic_to_shared(Bs + r*24 + cb*8);
        }
    }
    __syncthreads();

    for (int t = 0; t < SP; t++) {
        float acc[2][8][4];
        #pragma unroll
        for (int i = 0; i < 2; i++)
            #pragma unroll
            for (int j = 0; j < 8; j++)
                #pragma unroll
                for (int q = 0; q < 4; q++) acc[i][j][q] = 0.0f;

        for (int kk = 0; kk < 8; kk++) {
            /* stage Whh k16-slab: rows tid, cc 0/1 */
            #pragma unroll
            for (int j = 0; j < 2; j++)
                *(int4*)(Bs + tid*24 + j*8) =
                    *(const int4*)(Whh + (size_t)tid*128 + kk*16 + j*8);
            __syncthreads();

            uint32_t a[2][4];
            #pragma unroll
            for (int mi = 0; mi < 2; mi++) {
                uint32_t ad = hBase[mi] + (uint32_t)((((2*kk + hCh) ^ hS[mi]))<<4);
                ldsm4(a[mi], ad);
            }
            #pragma unroll
            for (int nig = 0; nig < 4; nig++) {
                uint32_t bb[4];
                ldsm4(bb, bAddr[nig]);
                mma16(acc[0][nig*2],   a[0], bb[0], bb[1]);
                mma16(acc[1][nig*2],   a[1], bb[0], bb[1]);
                mma16(acc[0][nig*2+1], a[0], bb[2], bb[3]);
                mma16(acc[1][nig*2+1], a[1], bb[2], bb[3]);
            }
            __syncthreads();
        }

        /* epilogue: add xw, exchange gates, cell update */
        #pragma unroll
        for (int mi = 0; mi < 2; mi++) {
            int rbl = wm*32 + mi*16 + g;
            #pragma unroll
            for (int ni = 0; ni < 8; ni++) {
                int col = wn*64 + ni*8 + 2*tig;
                size_t x0 = ((size_t)(b0+rbl  )*SP + t)*512 + col;
                size_t x1 = ((size_t)(b0+rbl+8)*SP + t)*512 + col;
                float c0 = acc[mi][ni][0] + xw[x0];
                float c1 = acc[mi][ni][1] + xw[x0+1];
                float c2 = acc[mi][ni][2] + xw[x1];
                float c3 = acc[mi][ni][3] + xw[x1+1];
                float r0 = __shfl_xor_sync(0xffffffffu, c0, 1);
                float r1 = __shfl_xor_sync(0xffffffffu, c1, 1);
                float r2 = __shfl_xor_sync(0xffffffffu, c2, 1);
                float r3 = __shfl_xor_sync(0xffffffffu, c3, 1);
                int u = col >> 2;
                int rowl; float ig, fg, gg, og;
                if ((tig & 1) == 0) { ig = c0; fg = c1; gg = r0; og = r1; rowl = rbl; }
                else                { gg = c2; og = c3; ig = r2; fg = r3; rowl = rbl+8; }
                float cold = c_reg[mi*8+ni];
                float cn = sigm(fg)*cold + sigm(ig)*tanhf(gg);
                float hn = sigm(og)*tanhf(cn);
                c_reg[mi*8+ni] = cn;
                __half hh = __float2half(hn);
                Hs[rowl*128 + (((u>>3) ^ (rowl&7))<<3) + (u&7)] = hh;
                size_t yi = ((size_t)(b0+rowl)*SP + t)*NC + u;
                if (ysHalf) ((__half*)ysv)[yi] = hh;
                else        ((float*)ysv)[yi] = hn;
            }
        }
    }
    __syncthreads();

    for (int i = tid; i < 64*128; i += 512) {
        int m = i>>7, k = i&127;
        g_h0[(b0+m)*NC + k] =
            __half2float(Hs[m*128 + (((k>>3) ^ (m&7))<<3) + (k&7)]);
    }
    #pragma unroll
    for (int mi = 0; mi < 2; mi++)
        #pragma unroll
        for (int ni = 0; ni < 8; ni++) {
            int rowl = wm*32 + mi*16 + g + ((tig & 1) ? 8 : 0);
            int u    = (wn*64 + ni*8 + 2*tig) >> 2;
            g_c[(b0+rowl)*NC + u] = c_reg[mi*8+ni];
        }
}

/* ---------------- output projection + rescale ---------------------- */
__global__ void out_kernel(const float* __restrict__ oW,
                           const float* __restrict__ ob,
                           float* __restrict__ out)
{
    int r    = blockIdx.x*8 + (threadIdx.x >> 5);
    int lane = threadIdx.x & 31;
    float s = 0.0f;
    #pragma unroll
    for (int k = 0; k < 4; k++)
        s += g_dec[(size_t)r*NC + lane + 32*k]*oW[lane + 32*k];
    #pragma unroll
    for (int o = 16; o; o >>= 1) s += __shfl_down_sync(0xffffffffu, s, o);
    if (lane == 0)
        out[r] = (s + ob[0])*g_scale[r/SP];
}

/* ---------------- host driver -------------------------------------- */
extern "C" void kernel_launch(void* const* d_in, const int* in_sizes, int n_in,
                              void* d_out, int out_size)
{
    const int*   cat   = (const int*)  d_in[0];
    const float* sreal = (const float*)d_in[1];
    const float* ptf   = (const float*)d_in[2];
    const float* pt    = (const float*)d_in[3];
    const float* pov   = (const float*)d_in[4];
    const float* ftf   = (const float*)d_in[5];
    const float* emb   = (const float*)d_in[6];
    const float* gWih  = (const float*)d_in[7];
    const float* gWhh  = (const float*)d_in[8];
    const float* gbih  = (const float*)d_in[9];
    const float* gbhh  = (const float*)d_in[10];
    const float* eWih  = (const float*)d_in[11];
    const float* eWhh  = (const float*)d_in[12];
    const float* eb    = (const float*)d_in[13];
    const float* dWih  = (const float*)d_in[14];
    const float* dWhh  = (const float*)d_in[15];
    const float* db    = (const float*)d_in[16];
    const float* oW    = (const float*)d_in[17];
    const float* ob    = (const float*)d_in[18];
    float* out = (float*)d_out;

    float *p_xw, *p_dec, *p_bcat, *p_eb, *p_db;
    __half *p_hv, *p_enc, *p_Wcat, *p_eWih, *p_eWhh, *p_dWih, *p_dWhh;
    cudaGetSymbolAddress((void**)&p_xw,   g_xw);
    cudaGetSymbolAddress((void**)&p_dec,  g_dec);
    cudaGetSymbolAddress((void**)&p_hv,   g_hv);
    cudaGetSymbolAddress((void**)&p_enc,  g_enc);
    cudaGetSymbolAddress((void**)&p_Wcat, g_Wcat);
    cudaGetSymbolAddress((void**)&p_bcat, g_bcat);
    cudaGetSymbolAddress((void**)&p_eWih, g_eWih);
    cudaGetSymbolAddress((void**)&p_eWhh, g_eWhh);
    cudaGetSymbolAddress((void**)&p_eb,   g_eb);
    cudaGetSymbolAddress((void**)&p_dWih, g_dWih);
    cudaGetSymbolAddress((void**)&p_dWhh, g_dWhh);
    cudaGetSymbolAddress((void**)&p_db,   g_db);

    dim3 gGrid(NROWS/128, 4), gThr(256);

    row_stats<<<BATCH/8, 256>>>(pt, pov);
    pack_gru<<<(512*KCAT + 255)/256, 256>>>(gWih, gWhh, gbih, gbhh);
    pack_enc<<<(NSEG*512*128 + 255)/256, 256>>>(eWih, eWhh, eb);
    build_inputs<<<BATCH, 192>>>(cat, sreal, ptf, pt, emb);

    /* seg 0: GRU over x only (h==0), K=32 */
    gemm_fp16<<<gGrid, gThr>>>(3, 0, nullptr, 32, KCAT,
                               p_Wcat + 128, p_bcat, nullptr, 1, 1);
    /* seg 0 LSTM input projection (ncu capture region) */
    gemm_fp16<<<gGrid, gThr>>>(0, 0, p_hv, NC, NC,
                               p_eWih, p_eb, p_xw, 0, 0);
    build_extra<<<(NROWS + 255)/256, 256>>>(ftf);
    pack_dec<<<(512*KQP + 255)/256, 256>>>(dWih, dWhh, db);
    lstm_seq<<<BATCH/64, 512>>>(p_eWhh, p_xw, p_enc, 1, 1);

    for (int i = 1; i < NSEG; i++) {
        gemm_fp16<<<gGrid, gThr>>>(1, i, nullptr, KCAT, KCAT,
                                   p_Wcat, p_bcat, nullptr, 1, 0);
        gemm_fp16<<<gGrid, gThr>>>(0, 0, p_hv, NC, NC,
                                   p_eWih + (size_t)i*512*128,
                                   p_eb + i*512, p_xw, 0, 0);
        lstm_seq<<<BATCH/64, 512>>>(p_eWhh + (size_t)i*512*128, p_xw, p_enc, 0, 1);
    }

    /* decoder: query [enc|x|extra], K=192 */
    gemm_fp16<<<gGrid, gThr>>>(2, 0, nullptr, KQP, KQP,
                               p_dWih, p_db, p_xw, 0, 0);
    lstm_seq<<<BATCH/64, 512>>>(p_dWhh, p_xw, p_dec, 0, 0);

    out_kernel<<<NROWS/8, 256>>>(oW, ob, out);
}

// round 15
// speedup vs baseline: 5.4551x; 1.2947x over previous
#include <cuda_runtime.h>
#include <cuda_fp16.h>
#include <math.h>
#include <stdint.h>

#define BATCH 8192
#define CTX   168
#define SP    24
#define HIST  336
#define NC    128
#define NSEG  7
#define NROWS (BATCH*SP)
#define KCAT  160     /* [h 128 | x 30 | pad 2] */
#define KQP   192     /* [h 128 | x 32 | extra 32] */

/* lstm_seq dynamic smem: Ws 512 rows x 136 halves + Hs 64x128 halves */
#define WS_PAD 136
#define LSTM_SMEM (512*WS_PAD*2 + 64*128*2)

/* scratch (device globals; allocation-free, replay-safe) */
__device__ __align__(16) __half g_inputs[BATCH*CTX*32];
__device__ __align__(16) __half g_extra[(size_t)NROWS*32];
__device__ __align__(16) __half g_xw[(size_t)NROWS*512];
__device__ __align__(16) __half g_hv[(size_t)NROWS*NC];
__device__ __align__(16) __half g_enc[(size_t)NROWS*NC];
__device__ float  g_dec[(size_t)NROWS*NC];
__device__ float  g_h0[BATCH*NC];
__device__ float  g_c[BATCH*NC];
__device__ float  g_scale[BATCH];
__device__ float  g_wsum[BATCH];
__device__ float  g_wcnt[BATCH];
__device__ float  g_static[BATCH*18];
__device__ float  g_part[2048];
__device__ float  g_tot[2];
/* packed weights, fp16; row = unit*4 + gate */
__device__ __align__(16) __half g_Wcat[512*KCAT];
__device__ float  g_bcat[512];
__device__ __align__(16) __half g_eWih[NSEG*512*NC];
__device__ __align__(16) __half g_eWhh[NSEG*512*NC];
__device__ float  g_eb[NSEG*512];
__device__ __align__(16) __half g_dWih[512*KQP];
__device__ __align__(16) __half g_dWhh[512*NC];
__device__ float  g_db[512];

__device__ __forceinline__ float tanh_fast(float x){
    float y; asm("tanh.approx.f32 %0, %1;" : "=f"(y) : "f"(x)); return y;
}
__device__ __forceinline__ float sigm_fast(float x){
    return fmaf(0.5f, tanh_fast(0.5f*x), 0.5f);
}

__device__ __forceinline__ void ldsm4(uint32_t* r, uint32_t sa){
    asm volatile("ldmatrix.sync.aligned.m8n8.x4.shared.b16 {%0,%1,%2,%3}, [%4];"
        : "=r"(r[0]),"=r"(r[1]),"=r"(r[2]),"=r"(r[3]) : "r"(sa));
}
__device__ __forceinline__ void mma16(float* c, const uint32_t* a, uint32_t b0, uint32_t b1){
    asm volatile("mma.sync.aligned.m16n8k16.row.col.f32.f16.f16.f32 "
        "{%0,%1,%2,%3}, {%4,%5,%6,%7}, {%8,%9}, {%0,%1,%2,%3};\n"
        : "+f"(c[0]),"+f"(c[1]),"+f"(c[2]),"+f"(c[3])
        : "r"(a[0]),"r"(a[1]),"r"(a[2]),"r"(a[3]), "r"(b0),"r"(b1));
}

/* ---------------- stats ---------------- */
__global__ void row_stats(const float* __restrict__ pt,
                          const float* __restrict__ pov)
{
    __shared__ float pws[8], pwc[8];
    int w    = threadIdx.x >> 5;
    int b    = blockIdx.x*8 + w;
    int lane = threadIdx.x & 31;
    float ws = 0.0f, wc = 0.0f;
    for (int t = lane; t < CTX; t += 32) {
        float wv = pov[b*HIST + CTX + t];
        float d  = pt [b*HIST + CTX + t];
        ws += fabsf(d)*wv;  wc += wv;
    }
    #pragma unroll
    for (int o = 16; o; o >>= 1) {
        ws += __shfl_down_sync(0xffffffffu, ws, o);
        wc += __shfl_down_sync(0xffffffffu, wc, o);
    }
    if (lane == 0) {
        g_wsum[b] = ws;  g_wcnt[b] = wc;
        pws[w] = ws;  pwc[w] = wc;
    }
    __syncthreads();
    if (threadIdx.x == 0) {
        float a = 0.0f, c = 0.0f;
        #pragma unroll
        for (int i = 0; i < 8; i++) { a += pws[i]; c += pwc[i]; }
        g_part[2*blockIdx.x]   = a;
        g_part[2*blockIdx.x+1] = c;
    }
}

/* ---------------- pack GRU weights [h128|x30|00] + totals ----------- */
__global__ void pack_gru(const float* __restrict__ gWih, const float* __restrict__ gWhh,
                         const float* __restrict__ gbih, const float* __restrict__ gbhh)
{
    if (blockIdx.x == 0) {
        __shared__ float r0[256], r1[256];
        int tid = threadIdx.x;
        float s0 = 0.0f, s1 = 0.0f;
        for (int i = tid; i < 1024; i += 256) {
            s0 += g_part[2*i];  s1 += g_part[2*i+1];
        }
        r0[tid] = s0;  r1[tid] = s1;
        __syncthreads();
        for (int o = 128; o; o >>= 1) {
            if (tid < o) { r0[tid] += r0[tid+o]; r1[tid] += r1[tid+o]; }
            __syncthreads();
        }
        if (tid == 0) { g_tot[0] = r0[0];  g_tot[1] = r1[0]; }
    }
    int idx = blockIdx.x*blockDim.x + threadIdx.x;
    if (idx < 512) {
        int u = idx>>2, gg = idx&3;  float bv;
        if      (gg == 0) bv = gbih[u]     + gbhh[u];
        else if (gg == 1) bv = gbih[128+u] + gbhh[128+u];
        else if (gg == 2) bv = gbih[256+u];
        else              bv = gbhh[256+u];
        g_bcat[idx] = bv;
    }
    if (idx >= 512*KCAT) return;
    int pr = idx/KCAT, k = idx%KCAT;
    int u = pr>>2, gg = pr&3;
    float v = 0.0f;
    if (k < 128) {
        if      (gg == 0) v = gWhh[u*128 + k];
        else if (gg == 1) v = gWhh[(128+u)*128 + k];
        else if (gg == 3) v = gWhh[(256+u)*128 + k];
    } else if (k < 158) {
        int xk = k - 128;
        if      (gg == 0) v = gWih[u*30 + xk];
        else if (gg == 1) v = gWih[(128+u)*30 + xk];
        else if (gg == 2) v = gWih[(256+u)*30 + xk];
    }
    g_Wcat[idx] = __float2half(v);
}

/* ---------------- scale + static + input tensor (fp16) -------------- */
__global__ void build_inputs(const int*   __restrict__ cat,
                             const float* __restrict__ sreal,
                             const float* __restrict__ ptf,
                             const float* __restrict__ pt,
                             const float* __restrict__ emb)
{
    int b = blockIdx.x;
    __shared__ float s_scale;
    __shared__ float s_static[18];
    if (threadIdx.x == 0) {
        float ws  = g_wsum[b], wc = g_wcnt[b];
        float def = g_tot[0] / fmaxf(g_tot[1], 1.0f);
        float sc  = ws / fmaxf(wc, 1.0f);
        sc = (ws > 0.0f) ? sc : def;
        sc = fmaxf(1e-10f, sc);
        s_scale = sc;  g_scale[b] = sc;
    }
    __syncthreads();
    if (threadIdx.x < 18) {
        int c = threadIdx.x;  float v;
        if (c < 16)       v = emb[cat[b]*16 + c];
        else if (c == 16) v = sreal[b];
        else              v = logf(s_scale);
        s_static[c] = v;  g_static[b*18 + c] = v;
    }
    __syncthreads();
    float inv = 1.0f / s_scale;
    const int lagv[8] = {24,48,72,96,120,144,168,0};
    for (int t = threadIdx.x; t < CTX; t += blockDim.x) {
        __half* o = &g_inputs[(b*CTX + t)*32];
        #pragma unroll
        for (int l = 0; l < 8; l++)
            o[l] = __float2half(pt[b*HIST + (CTX - lagv[l]) + t]*inv);
        #pragma unroll
        for (int f = 0; f < 4; f++)
            o[8+f] = __float2half(ptf[(b*HIST + CTX + t)*4 + f]);
        #pragma unroll
        for (int c = 0; c < 18; c++)
            o[12+c] = __float2half(s_static[c]);
        o[30] = __float2half(0.0f);  o[31] = __float2half(0.0f);
    }
}

/* ---------------- decoder extras: [ftf4|static18|pad10] ------------- */
__global__ void build_extra(const float* __restrict__ ftf)
{
    int r = blockIdx.x*blockDim.x + threadIdx.x;
    if (r >= NROWS) return;
    int b = r/SP;
    __half* e = &g_extra[(size_t)r*32];
    #pragma unroll
    for (int q = 0; q < 4; q++)  e[q] = __float2half(ftf[r*4 + q]);
    #pragma unroll
    for (int c = 0; c < 18; c++) e[4+c] = __float2half(g_static[b*18 + c]);
    #pragma unroll
    for (int c = 22; c < 32; c++) e[c] = __float2half(0.0f);
}

/* ---------------- pack encoder / decoder weights (fp16) -------------- */
__global__ void pack_enc(const float* __restrict__ eWih, const float* __restrict__ eWhh,
                         const float* __restrict__ eb)
{
    int idx = blockIdx.x*blockDim.x + threadIdx.x;
    if (idx >= NSEG*512*128) return;
    int s  = idx / (512*128);
    int r2 = idx % (512*128);
    int pr = r2 / 128, k = r2 % 128;
    int orig = (pr&3)*128 + (pr>>2);
    g_eWih[idx] = __float2half(eWih[(size_t)s*512*128 + orig*128 + k]);
    g_eWhh[idx] = __float2half(eWhh[(size_t)s*512*128 + orig*128 + k]);
    if (k == 0) g_eb[s*512 + pr] = eb[s*512 + orig];
}

__global__ void pack_dec(const float* __restrict__ dWih, const float* __restrict__ dWhh,
                         const float* __restrict__ db)
{
    int idx = blockIdx.x*blockDim.x + threadIdx.x;
    if (idx >= 512*KQP) return;
    int pr = idx/KQP, k = idx%KQP;
    int orig = (pr&3)*128 + (pr>>2);
    float v = 0.0f;
    if (k < 128)       v = dWih[orig*180 + 30 + k];
    else if (k < 158)  v = dWih[orig*180 + (k-128)];
    else if (k < 160)  v = 0.0f;
    else if (k < 164)  v = dWih[orig*180 + 158 + (k-160)];
    else if (k < 182)  v = dWih[orig*180 + 162 + (k-164)];
    g_dWih[idx] = __float2half(v);
    if (k < 128) g_dWhh[pr*128 + k] = __float2half(dWhh[orig*128 + k]);
    if (k == 0)  g_db[pr] = db[orig];
}

/* ------------------------------------------------------------------ */
/* fp16 GEMM, 128x128 tile, BK=32, 256 thr, ldmatrix + m16n8k16        */
/* aMode: 0=A[r*ldw+k]; 1=GRU [h|x]; 2=query [h|x|extra]; 3=x-only     */
/* epi:   0=bias+store C fp16 (ldc=512); 1=GRU combine -> g_hv (half)  */
/* ------------------------------------------------------------------ */
__global__ __launch_bounds__(256,2) void gemm_fp16(
    int aMode, int seg,
    const __half* __restrict__ A, int K, int ldw,
    const __half* __restrict__ W, const float* __restrict__ bias,
    __half* __restrict__ C, int epi, int zeroH)
{
    __shared__ __align__(16) __half Asm[128*40];
    __shared__ __align__(16) __half Bsm[128*40];
    __shared__ int4 rowinfo[128];

    int tid = threadIdx.x;
    int m0 = blockIdx.x*128, n0 = blockIdx.y*128;
    int w = tid>>5, lane = tid&31;
    int wm = w>>2, wn = w&3;
    int g = lane>>2, tig = lane&3;

    if (aMode != 0 && tid < 128) {
        int r = m0 + tid;
        int b = r/SP, t = r - b*SP;
        rowinfo[tid] = make_int4((b*CTX + seg*SP + t)*32, r*NC, r*32, 0);
    }

    uint32_t aAddr[4], bAddr[2];
    {
        int rl = lane&15, ch = lane>>4;
        #pragma unroll
        for (int mi = 0; mi < 4; mi++) {
            int r = wm*64 + mi*16 + rl;
            aAddr[mi] = (uint32_t)__cvta_generic_to_shared(Asm + r*40 + ch*8);
        }
        int rb0 = (lane&7) + ((lane&16)>>1);
        int cb  = (lane>>3)&1;
        #pragma unroll
        for (int nig = 0; nig < 2; nig++) {
            int r = wn*32 + nig*16 + rb0;
            bAddr[nig] = (uint32_t)__cvta_generic_to_shared(Bsm + r*40 + cb*8);
        }
    }

    float acc[4][4][4];
    #pragma unroll
    for (int i = 0; i < 4; i++)
        #pragma unroll
        for (int j = 0; j < 4; j++)
            #pragma unroll
            for (int q = 0; q < 4; q++) acc[i][j][q] = 0.0f;

    int srow = tid>>2, scc = tid&3;
    if (aMode != 0) __syncthreads();

    for (int k0 = 0; k0 < K; k0 += 32) {
        int k = k0 + scc*8;
        #pragma unroll
        for (int j = 0; j < 2; j++) {
            int row = srow + j*64;
            const __half* src;
            if (aMode == 0)       src = A + (size_t)(m0+row)*ldw + k;
            else {
                int4 ri = rowinfo[row];
                if (aMode == 3)     src = g_inputs + ri.x + k;
                else if (k < 128)   src = g_enc + (size_t)ri.y + k;
                else if (k < 160)   src = g_inputs + ri.x + (k-128);
                else                src = g_extra + (size_t)ri.z + (k-160);
            }
            *(int4*)(Asm + row*40 + scc*8) = *(const int4*)src;
            *(int4*)(Bsm + row*40 + scc*8) = *(const int4*)(W + (size_t)(n0+row)*ldw + k);
        }
        __syncthreads();
        #pragma unroll
        for (int kk = 0; kk < 2; kk++) {
            uint32_t a[4][4];
            #pragma unroll
            for (int mi = 0; mi < 4; mi++) ldsm4(a[mi], aAddr[mi] + kk*32);
            #pragma unroll
            for (int nig = 0; nig < 2; nig++) {
                uint32_t bb[4];
                ldsm4(bb, bAddr[nig] + kk*32);
                #pragma unroll
                for (int mi = 0; mi < 4; mi++) {
                    mma16(acc[mi][nig*2],   a[mi], bb[0], bb[1]);
                    mma16(acc[mi][nig*2+1], a[mi], bb[2], bb[3]);
                }
            }
        }
        __syncthreads();
    }

    if (epi == 0) {
        #pragma unroll
        for (int mi = 0; mi < 4; mi++) {
            int row = m0 + wm*64 + mi*16 + g;
            #pragma unroll
            for (int ni = 0; ni < 4; ni++) {
                int col = n0 + wn*32 + ni*8 + 2*tig;
                float b0 = bias[col], b1 = bias[col+1];
                *(__half2*)&C[(size_t)row*512 + col] =
                    __floats2half2_rn(acc[mi][ni][0]+b0, acc[mi][ni][1]+b1);
                *(__half2*)&C[(size_t)(row+8)*512 + col] =
                    __floats2half2_rn(acc[mi][ni][2]+b0, acc[mi][ni][3]+b1);
            }
        }
    } else {
        #pragma unroll
        for (int mi = 0; mi < 4; mi++) {
            int rowb = m0 + wm*64 + mi*16 + g;
            #pragma unroll
            for (int ni = 0; ni < 4; ni++) {
                int col = n0 + wn*32 + ni*8 + 2*tig;
                float b0 = bias[col], b1 = bias[col+1];
                float c0 = acc[mi][ni][0] + b0;
                float c1 = acc[mi][ni][1] + b1;
                float c2 = acc[mi][ni][2] + b0;
                float c3 = acc[mi][ni][3] + b1;
                float r0 = __shfl_xor_sync(0xffffffffu, c0, 1);
                float r1 = __shfl_xor_sync(0xffffffffu, c1, 1);
                float r2 = __shfl_xor_sync(0xffffffffu, c2, 1);
                float r3 = __shfl_xor_sync(0xffffffffu, c3, 1);
                int u = col >> 2;
                int row; float rg, zg, ing, hng;
                if ((tig & 1) == 0) { rg = c0; zg = c1; ing = r0; hng = r1; row = rowb; }
                else                { ing = c2; hng = c3; rg = r2; zg = r3; row = rowb+8; }
                float rr = sigm_fast(rg), zz = sigm_fast(zg);
                float nn = tanh_fast(ing + rr*hng);
                float hold = zeroH ? 0.0f : __half2float(g_enc[(size_t)row*NC + u]);
                g_hv[(size_t)row*NC + u] = __float2half((1.0f - zz)*nn + zz*hold);
            }
        }
    }
}

/* ------------------------------------------------------------------ */
/* fused fp16 LSTM sequence: Whh fully resident in smem, 24 steps,     */
/* 64 rows/block, 512 thr (16 warps 2x8, warp tile 32x64).             */
/* Dynamic smem: Ws[512][136] + Hs[64][128] (swizzled).                */
/* ------------------------------------------------------------------ */
__global__ __launch_bounds__(512) void lstm_seq(
    const __half* __restrict__ Whh,   /* packed [512][128] */
    const __half* __restrict__ xw,    /* [NROWS][512] fp16, bias folded */
    void*         __restrict__ ysv,
    int initHC, int ysHalf)
{
    extern __shared__ __align__(16) __half smem[];
    __half* Ws = smem;                 /* 512 x WS_PAD */
    __half* Hs = smem + 512*WS_PAD;    /* 64 x 128 swizzled */

    int tid = threadIdx.x;
    int b0 = blockIdx.x*64;
    int w = tid>>5, lane = tid&31;
    int wm = w>>3, wn = w&7;
    int g = lane>>2, tig = lane&3;

    /* load Whh once (16 int4 per thread) */
    #pragma unroll
    for (int i = 0; i < 16; i++) {
        int idx = tid + i*512;             /* 0..8191 = row*16chunks */
        int row = idx >> 4, ch = idx & 15;
        *(int4*)(Ws + row*WS_PAD + ch*8) =
            *(const int4*)(Whh + (size_t)row*128 + ch*8);
    }

    for (int i = tid; i < 64*128; i += 512) {
        int m = i>>7, k = i&127;
        float hv = initHC ? 0.0f : g_h0[(b0+m)*NC + k];
        Hs[m*128 + (((k>>3) ^ (m&7))<<3) + (k&7)] = __float2half(hv);
    }
    float c_reg[16];
    #pragma unroll
    for (int mi = 0; mi < 2; mi++)
        #pragma unroll
        for (int ni = 0; ni < 8; ni++) {
            int rowl = wm*32 + mi*16 + g + ((tig & 1) ? 8 : 0);
            int u    = (wn*64 + ni*8 + 2*tig) >> 2;
            c_reg[mi*8+ni] = initHC ? 0.0f : g_c[(b0+rowl)*NC + u];
        }

    /* LDSM address bases */
    uint32_t hBase[2]; int hS[2]; int hCh = lane>>4;
    {
        int rl = lane&15;
        #pragma unroll
        for (int mi = 0; mi < 2; mi++) {
            int r = wm*32 + mi*16 + rl;
            hBase[mi] = (uint32_t)__cvta_generic_to_shared(Hs + r*128);
            hS[mi] = r & 7;
        }
    }
    uint32_t bAddr[4];
    {
        int rb0 = (lane&7) + ((lane&16)>>1);
        int cb  = (lane>>3)&1;
        #pragma unroll
        for (int nig = 0; nig < 4; nig++) {
            int r = wn*64 + nig*16 + rb0;
            bAddr[nig] = (uint32_t)__cvta_generic_to_shared(Ws + r*WS_PAD + cb*8);
        }
    }
    __syncthreads();

    for (int t = 0; t < SP; t++) {
        float acc[2][8][4];
        #pragma unroll
        for (int i = 0; i < 2; i++)
            #pragma unroll
            for (int j = 0; j < 8; j++)
                #pragma unroll
                for (int q = 0; q < 4; q++) acc[i][j][q] = 0.0f;

        #pragma unroll
        for (int kk = 0; kk < 8; kk++) {
            uint32_t a[2][4];
            #pragma unroll
            for (int mi = 0; mi < 2; mi++) {
                uint32_t ad = hBase[mi] + (uint32_t)((((2*kk + hCh) ^ hS[mi]))<<4);
                ldsm4(a[mi], ad);
            }
            #pragma unroll
            for (int nig = 0; nig < 4; nig++) {
                uint32_t bb[4];
                ldsm4(bb, bAddr[nig] + kk*32);
                mma16(acc[0][nig*2],   a[0], bb[0], bb[1]);
                mma16(acc[1][nig*2],   a[1], bb[0], bb[1]);
                mma16(acc[0][nig*2+1], a[0], bb[2], bb[3]);
                mma16(acc[1][nig*2+1], a[1], bb[2], bb[3]);
            }
        }
        __syncthreads();   /* all Hs reads done before epilogue writes */

        #pragma unroll
        for (int mi = 0; mi < 2; mi++) {
            int rbl = wm*32 + mi*16 + g;
            #pragma unroll
            for (int ni = 0; ni < 8; ni++) {
                int col = wn*64 + ni*8 + 2*tig;
                size_t x0 = ((size_t)(b0+rbl  )*SP + t)*512 + col;
                size_t x1 = ((size_t)(b0+rbl+8)*SP + t)*512 + col;
                float2 xv0 = __half22float2(*(const __half2*)&xw[x0]);
                float2 xv1 = __half22float2(*(const __half2*)&xw[x1]);
                float c0 = acc[mi][ni][0] + xv0.x;
                float c1 = acc[mi][ni][1] + xv0.y;
                float c2 = acc[mi][ni][2] + xv1.x;
                float c3 = acc[mi][ni][3] + xv1.y;
                float r0 = __shfl_xor_sync(0xffffffffu, c0, 1);
                float r1 = __shfl_xor_sync(0xffffffffu, c1, 1);
                float r2 = __shfl_xor_sync(0xffffffffu, c2, 1);
                float r3 = __shfl_xor_sync(0xffffffffu, c3, 1);
                int u = col >> 2;
                int rowl; float ig, fg, gg, og;
                if ((tig & 1) == 0) { ig = c0; fg = c1; gg = r0; og = r1; rowl = rbl; }
                else                { gg = c2; og = c3; ig = r2; fg = r3; rowl = rbl+8; }
                float cold = c_reg[mi*8+ni];
                float cn = sigm_fast(fg)*cold + sigm_fast(ig)*tanh_fast(gg);
                float hn = sigm_fast(og)*tanh_fast(cn);
                c_reg[mi*8+ni] = cn;
                __half hh = __float2half(hn);
                Hs[rowl*128 + (((u>>3) ^ (rowl&7))<<3) + (u&7)] = hh;
                size_t yi = ((size_t)(b0+rowl)*SP + t)*NC + u;
                if (ysHalf) ((__half*)ysv)[yi] = hh;
                else        ((float*)ysv)[yi] = hn;
            }
        }
        __syncthreads();   /* Hs writes visible before next step's ldsm */
    }

    for (int i = tid; i < 64*128; i += 512) {
        int m = i>>7, k = i&127;
        g_h0[(b0+m)*NC + k] =
            __half2float(Hs[m*128 + (((k>>3) ^ (m&7))<<3) + (k&7)]);
    }
    #pragma unroll
    for (int mi = 0; mi < 2; mi++)
        #pragma unroll
        for (int ni = 0; ni < 8; ni++) {
            int rowl = wm*32 + mi*16 + g + ((tig & 1) ? 8 : 0);
            int u    = (wn*64 + ni*8 + 2*tig) >> 2;
            g_c[(b0+rowl)*NC + u] = c_reg[mi*8+ni];
        }
}

/* ---------------- output projection + rescale ---------------------- */
__global__ void out_kernel(const float* __restrict__ oW,
                           const float* __restrict__ ob,
                           float* __restrict__ out)
{
    int r    = blockIdx.x*8 + (threadIdx.x >> 5);
    int lane = threadIdx.x & 31;
    float s = 0.0f;
    #pragma unroll
    for (int k = 0; k < 4; k++)
        s += g_dec[(size_t)r*NC + lane + 32*k]*oW[lane + 32*k];
    #pragma unroll
    for (int o = 16; o; o >>= 1) s += __shfl_down_sync(0xffffffffu, s, o);
    if (lane == 0)
        out[r] = (s + ob[0])*g_scale[r/SP];
}

/* ---------------- host driver -------------------------------------- */
extern "C" void kernel_launch(void* const* d_in, const int* in_sizes, int n_in,
                              void* d_out, int out_size)
{
    const int*   cat   = (const int*)  d_in[0];
    const float* sreal = (const float*)d_in[1];
    const float* ptf   = (const float*)d_in[2];
    const float* pt    = (const float*)d_in[3];
    const float* pov   = (const float*)d_in[4];
    const float* ftf   = (const float*)d_in[5];
    const float* emb   = (const float*)d_in[6];
    const float* gWih  = (const float*)d_in[7];
    const float* gWhh  = (const float*)d_in[8];
    const float* gbih  = (const float*)d_in[9];
    const float* gbhh  = (const float*)d_in[10];
    const float* eWih  = (const float*)d_in[11];
    const float* eWhh  = (const float*)d_in[12];
    const float* eb    = (const float*)d_in[13];
    const float* dWih  = (const float*)d_in[14];
    const float* dWhh  = (const float*)d_in[15];
    const float* db    = (const float*)d_in[16];
    const float* oW    = (const float*)d_in[17];
    const float* ob    = (const float*)d_in[18];
    float* out = (float*)d_out;

    float *p_dec, *p_bcat, *p_eb, *p_db;
    __half *p_xw, *p_hv, *p_enc, *p_Wcat, *p_eWih, *p_eWhh, *p_dWih, *p_dWhh;
    cudaGetSymbolAddress((void**)&p_xw,   g_xw);
    cudaGetSymbolAddress((void**)&p_dec,  g_dec);
    cudaGetSymbolAddress((void**)&p_hv,   g_hv);
    cudaGetSymbolAddress((void**)&p_enc,  g_enc);
    cudaGetSymbolAddress((void**)&p_Wcat, g_Wcat);
    cudaGetSymbolAddress((void**)&p_bcat, g_bcat);
    cudaGetSymbolAddress((void**)&p_eWih, g_eWih);
    cudaGetSymbolAddress((void**)&p_eWhh, g_eWhh);
    cudaGetSymbolAddress((void**)&p_eb,   g_eb);
    cudaGetSymbolAddress((void**)&p_dWih, g_dWih);
    cudaGetSymbolAddress((void**)&p_dWhh, g_dWhh);
    cudaGetSymbolAddress((void**)&p_db,   g_db);

    static int smem_set = 0;
    if (!smem_set) {
        cudaFuncSetAttribute(lstm_seq,
            cudaFuncAttributeMaxDynamicSharedMemorySize, LSTM_SMEM);
        smem_set = 1;
    }

    dim3 gGrid(NROWS/128, 4), gThr(256);

    row_stats<<<BATCH/8, 256>>>(pt, pov);
    pack_gru<<<(512*KCAT + 255)/256, 256>>>(gWih, gWhh, gbih, gbhh);
    pack_enc<<<(NSEG*512*128 + 255)/256, 256>>>(eWih, eWhh, eb);
    build_inputs<<<BATCH, 192>>>(cat, sreal, ptf, pt, emb);

    /* seg 0: GRU over x only (h==0), K=32 */
    gemm_fp16<<<gGrid, gThr>>>(3, 0, nullptr, 32, KCAT,
                               p_Wcat + 128, p_bcat, nullptr, 1, 1);
    /* seg 0 LSTM input projection */
    gemm_fp16<<<gGrid, gThr>>>(0, 0, p_hv, NC, NC,
                               p_eWih, p_eb, p_xw, 0, 0);
    build_extra<<<(NROWS + 255)/256, 256>>>(ftf);
    pack_dec<<<(512*KQP + 255)/256, 256>>>(dWih, dWhh, db);
    lstm_seq<<<BATCH/64, 512, LSTM_SMEM>>>(p_eWhh, p_xw, p_enc, 1, 1);

    for (int i = 1; i < NSEG; i++) {
        gemm_fp16<<<gGrid, gThr>>>(1, i, nullptr, KCAT, KCAT,
                                   p_Wcat, p_bcat, nullptr, 1, 0);
        gemm_fp16<<<gGrid, gThr>>>(0, 0, p_hv, NC, NC,
                                   p_eWih + (size_t)i*512*128,
                                   p_eb + i*512, p_xw, 0, 0);
        lstm_seq<<<BATCH/64, 512, LSTM_SMEM>>>(p_eWhh + (size_t)i*512*128,
                                               p_xw, p_enc, 0, 1);
    }

    /* decoder: query [enc|x|extra], K=192 */
    gemm_fp16<<<gGrid, gThr>>>(2, 0, nullptr, KQP, KQP,
                               p_dWih, p_db, p_xw, 0, 0);
    lstm_seq<<<BATCH/64, 512, LSTM_SMEM>>>(p_dWhh, p_xw, p_dec, 0, 0);

    out_kernel<<<NROWS/8, 256>>>(oW, ob, out);
}

// round 17
// speedup vs baseline: 6.0575x; 1.1104x over previous
#include <cuda_runtime.h>
#include <cuda_fp16.h>
#include <math.h>
#include <stdint.h>

#define BATCH 8192
#define CTX   168
#define SP    24
#define HIST  336
#define NC    128
#define NSEG  7
#define NROWS (BATCH*SP)
#define KCAT  160     /* [h 128 | x 30 | pad 2] */
#define KQP   192     /* [h 128 | x 32 | extra 32] */

/* lstm_seq dynamic smem: Ws 512x136 + Hs 2 x 64x128 (ping-pong) */
#define WS_PAD 136
#define LSTM_SMEM (512*WS_PAD*2 + 2*64*128*2)

/* gemm stage buffer: 128 rows x 40 halves, 2 stages */
#define GSTG (128*40)
#define GSTG_B (GSTG*2)   /* bytes per stage buffer */

/* scratch (device globals; allocation-free, replay-safe) */
__device__ __align__(16) __half g_inputs[BATCH*CTX*32];
__device__ __align__(16) __half g_extra[(size_t)NROWS*32];
__device__ __align__(16) __half g_xw[(size_t)NROWS*512];
__device__ __align__(16) __half g_hv[(size_t)NROWS*NC];
__device__ __align__(16) __half g_enc[(size_t)NROWS*NC];
__device__ __align__(16) __half g_dech[(size_t)NROWS*NC];
__device__ float  g_h0[BATCH*NC];
__device__ float  g_c[BATCH*NC];
__device__ float  g_scale[BATCH];
__device__ float  g_wsum[BATCH];
__device__ float  g_wcnt[BATCH];
__device__ float  g_static[BATCH*18];
__device__ float  g_part[2048];
__device__ float  g_tot[2];
/* packed weights, fp16; row = unit*4 + gate */
__device__ __align__(16) __half g_Wcat[512*KCAT];
__device__ float  g_bcat[512];
__device__ __align__(16) __half g_eWih[NSEG*512*NC];
__device__ __align__(16) __half g_eWhh[NSEG*512*NC];
__device__ float  g_eb[NSEG*512];
__device__ __align__(16) __half g_dWih[512*KQP];
__device__ __align__(16) __half g_dWhh[512*NC];
__device__ float  g_db[512];

__device__ __forceinline__ float tanh_fast(float x){
    float y; asm("tanh.approx.f32 %0, %1;" : "=f"(y) : "f"(x)); return y;
}
__device__ __forceinline__ float sigm_fast(float x){
    return fmaf(0.5f, tanh_fast(0.5f*x), 0.5f);
}
__device__ __forceinline__ void ldsm4(uint32_t* r, uint32_t sa){
    asm volatile("ldmatrix.sync.aligned.m8n8.x4.shared.b16 {%0,%1,%2,%3}, [%4];"
        : "=r"(r[0]),"=r"(r[1]),"=r"(r[2]),"=r"(r[3]) : "r"(sa));
}
__device__ __forceinline__ void mma16(float* c, const uint32_t* a, uint32_t b0, uint32_t b1){
    asm volatile("mma.sync.aligned.m16n8k16.row.col.f32.f16.f16.f32 "
        "{%0,%1,%2,%3}, {%4,%5,%6,%7}, {%8,%9}, {%0,%1,%2,%3};\n"
        : "+f"(c[0]),"+f"(c[1]),"+f"(c[2]),"+f"(c[3])
        : "r"(a[0]),"r"(a[1]),"r"(a[2]),"r"(a[3]), "r"(b0),"r"(b1));
}
__device__ __forceinline__ void cpa16(uint32_t dst, const void* src){
    asm volatile("cp.async.cg.shared.global [%0], [%1], 16;" :: "r"(dst), "l"(src));
}
__device__ __forceinline__ void cpa_commit(){
    asm volatile("cp.async.commit_group;");
}

/* ---------------- stats ---------------- */
__global__ void row_stats(const float* __restrict__ pt,
                          const float* __restrict__ pov)
{
    __shared__ float pws[8], pwc[8];
    int w    = threadIdx.x >> 5;
    int b    = blockIdx.x*8 + w;
    int lane = threadIdx.x & 31;
    float ws = 0.0f, wc = 0.0f;
    for (int t = lane; t < CTX; t += 32) {
        float wv = pov[b*HIST + CTX + t];
        float d  = pt [b*HIST + CTX + t];
        ws += fabsf(d)*wv;  wc += wv;
    }
    #pragma unroll
    for (int o = 16; o; o >>= 1) {
        ws += __shfl_down_sync(0xffffffffu, ws, o);
        wc += __shfl_down_sync(0xffffffffu, wc, o);
    }
    if (lane == 0) {
        g_wsum[b] = ws;  g_wcnt[b] = wc;
        pws[w] = ws;  pwc[w] = wc;
    }
    __syncthreads();
    if (threadIdx.x == 0) {
        float a = 0.0f, c = 0.0f;
        #pragma unroll
        for (int i = 0; i < 8; i++) { a += pws[i]; c += pwc[i]; }
        g_part[2*blockIdx.x]   = a;
        g_part[2*blockIdx.x+1] = c;
    }
}

/* ---------------- pack GRU weights [h128|x30|00] + totals ----------- */
__global__ void pack_gru(const float* __restrict__ gWih, const float* __restrict__ gWhh,
                         const float* __restrict__ gbih, const float* __restrict__ gbhh)
{
    if (blockIdx.x == 0) {
        __shared__ float r0[256], r1[256];
        int tid = threadIdx.x;
        float s0 = 0.0f, s1 = 0.0f;
        for (int i = tid; i < 1024; i += 256) {
            s0 += g_part[2*i];  s1 += g_part[2*i+1];
        }
        r0[tid] = s0;  r1[tid] = s1;
        __syncthreads();
        for (int o = 128; o; o >>= 1) {
            if (tid < o) { r0[tid] += r0[tid+o]; r1[tid] += r1[tid+o]; }
            __syncthreads();
        }
        if (tid == 0) { g_tot[0] = r0[0];  g_tot[1] = r1[0]; }
    }
    int idx = blockIdx.x*blockDim.x + threadIdx.x;
    if (idx < 512) {
        int u = idx>>2, gg = idx&3;  float bv;
        if      (gg == 0) bv = gbih[u]     + gbhh[u];
        else if (gg == 1) bv = gbih[128+u] + gbhh[128+u];
        else if (gg == 2) bv = gbih[256+u];
        else              bv = gbhh[256+u];
        g_bcat[idx] = bv;
    }
    if (idx >= 512*KCAT) return;
    int pr = idx/KCAT, k = idx%KCAT;
    int u = pr>>2, gg = pr&3;
    float v = 0.0f;
    if (k < 128) {
        if      (gg == 0) v = gWhh[u*128 + k];
        else if (gg == 1) v = gWhh[(128+u)*128 + k];
        else if (gg == 3) v = gWhh[(256+u)*128 + k];
    } else if (k < 158) {
        int xk = k - 128;
        if      (gg == 0) v = gWih[u*30 + xk];
        else if (gg == 1) v = gWih[(128+u)*30 + xk];
        else if (gg == 2) v = gWih[(256+u)*30 + xk];
    }
    g_Wcat[idx] = __float2half(v);
}

/* ---------------- scale + static + input tensor (fp16) -------------- */
__global__ void build_inputs(const int*   __restrict__ cat,
                             const float* __restrict__ sreal,
                             const float* __restrict__ ptf,
                             const float* __restrict__ pt,
                             const float* __restrict__ emb)
{
    int b = blockIdx.x;
    __shared__ float s_scale;
    __shared__ float s_static[18];
    if (threadIdx.x == 0) {
        float ws  = g_wsum[b], wc = g_wcnt[b];
        float def = g_tot[0] / fmaxf(g_tot[1], 1.0f);
        float sc  = ws / fmaxf(wc, 1.0f);
        sc = (ws > 0.0f) ? sc : def;
        sc = fmaxf(1e-10f, sc);
        s_scale = sc;  g_scale[b] = sc;
    }
    __syncthreads();
    if (threadIdx.x < 18) {
        int c = threadIdx.x;  float v;
        if (c < 16)       v = emb[cat[b]*16 + c];
        else if (c == 16) v = sreal[b];
        else              v = logf(s_scale);
        s_static[c] = v;  g_static[b*18 + c] = v;
    }
    __syncthreads();
    float inv = 1.0f / s_scale;
    const int lagv[8] = {24,48,72,96,120,144,168,0};
    for (int t = threadIdx.x; t < CTX; t += blockDim.x) {
        __half* o = &g_inputs[(b*CTX + t)*32];
        #pragma unroll
        for (int l = 0; l < 8; l++)
            o[l] = __float2half(pt[b*HIST + (CTX - lagv[l]) + t]*inv);
        #pragma unroll
        for (int f = 0; f < 4; f++)
            o[8+f] = __float2half(ptf[(b*HIST + CTX + t)*4 + f]);
        #pragma unroll
        for (int c = 0; c < 18; c++)
            o[12+c] = __float2half(s_static[c]);
        o[30] = __float2half(0.0f);  o[31] = __float2half(0.0f);
    }
}

/* ---------------- decoder extras: [ftf4|static18|pad10] ------------- */
__global__ void build_extra(const float* __restrict__ ftf)
{
    int r = blockIdx.x*blockDim.x + threadIdx.x;
    if (r >= NROWS) return;
    int b = r/SP;
    __half* e = &g_extra[(size_t)r*32];
    #pragma unroll
    for (int q = 0; q < 4; q++)  e[q] = __float2half(ftf[r*4 + q]);
    #pragma unroll
    for (int c = 0; c < 18; c++) e[4+c] = __float2half(g_static[b*18 + c]);
    #pragma unroll
    for (int c = 22; c < 32; c++) e[c] = __float2half(0.0f);
}

/* ---------------- pack encoder / decoder weights (fp16) -------------- */
__global__ void pack_enc(const float* __restrict__ eWih, const float* __restrict__ eWhh,
                         const float* __restrict__ eb)
{
    int idx = blockIdx.x*blockDim.x + threadIdx.x;
    if (idx >= NSEG*512*128) return;
    int s  = idx / (512*128);
    int r2 = idx % (512*128);
    int pr = r2 / 128, k = r2 % 128;
    int orig = (pr&3)*128 + (pr>>2);
    g_eWih[idx] = __float2half(eWih[(size_t)s*512*128 + orig*128 + k]);
    g_eWhh[idx] = __float2half(eWhh[(size_t)s*512*128 + orig*128 + k]);
    if (k == 0) g_eb[s*512 + pr] = eb[s*512 + orig];
}

__global__ void pack_dec(const float* __restrict__ dWih, const float* __restrict__ dWhh,
                         const float* __restrict__ db)
{
    int idx = blockIdx.x*blockDim.x + threadIdx.x;
    if (idx >= 512*KQP) return;
    int pr = idx/KQP, k = idx%KQP;
    int orig = (pr&3)*128 + (pr>>2);
    float v = 0.0f;
    if (k < 128)       v = dWih[orig*180 + 30 + k];
    else if (k < 158)  v = dWih[orig*180 + (k-128)];
    else if (k < 160)  v = 0.0f;
    else if (k < 164)  v = dWih[orig*180 + 158 + (k-160)];
    else if (k < 182)  v = dWih[orig*180 + 162 + (k-164)];
    g_dWih[idx] = __float2half(v);
    if (k < 128) g_dWhh[pr*128 + k] = __float2half(dWhh[orig*128 + k]);
    if (k == 0)  g_db[pr] = db[orig];
}

/* ------------------------------------------------------------------ */
/* fp16 GEMM, 128x128 tile, BK=32, 256 thr, cp.async 2-stage pipeline  */
/* aMode: 0=A[r*ldw+k]; 1=GRU [h|x]; 2=query [h|x|extra]; 3=x-only     */
/* epi:   0=bias+store C fp16 (ldc=512); 1=GRU combine -> g_hv (half)  */
/* ------------------------------------------------------------------ */
__global__ __launch_bounds__(256,2) void gemm_fp16(
    int aMode, int seg,
    const __half* __restrict__ A, int K, int ldw,
    const __half* __restrict__ W, const float* __restrict__ bias,
    __half* __restrict__ C, int epi, int zeroH)
{
    __shared__ __align__(16) __half Asm[2*GSTG];
    __shared__ __align__(16) __half Bsm[2*GSTG];
    __shared__ int4 rowinfo[128];

    int tid = threadIdx.x;
    int m0 = blockIdx.x*128, n0 = blockIdx.y*128;
    int w = tid>>5, lane = tid&31;
    int wm = w>>2, wn = w&3;
    int g = lane>>2, tig = lane&3;
    int srow = tid>>2, scc = tid&3;

    if (aMode != 0 && tid < 128) {
        int r = m0 + tid;
        int b = r/SP, t = r - b*SP;
        rowinfo[tid] = make_int4((b*CTX + seg*SP + t)*32, r*NC, r*32, 0);
    }
    if (aMode != 0) __syncthreads();

    uint32_t aS = (uint32_t)__cvta_generic_to_shared(Asm);
    uint32_t bS = (uint32_t)__cvta_generic_to_shared(Bsm);

    uint32_t aAddr[4], bAddr[2];
    {
        int rl = lane&15, ch = lane>>4;
        #pragma unroll
        for (int mi = 0; mi < 4; mi++) {
            int r = wm*64 + mi*16 + rl;
            aAddr[mi] = (uint32_t)__cvta_generic_to_shared(Asm + r*40 + ch*8);
        }
        int rb0 = (lane&7) + ((lane&16)>>1);
        int cb  = (lane>>3)&1;
        #pragma unroll
        for (int nig = 0; nig < 2; nig++) {
            int r = wn*32 + nig*16 + rb0;
            bAddr[nig] = (uint32_t)__cvta_generic_to_shared(Bsm + r*40 + cb*8);
        }
    }

    float acc[4][4][4];
    #pragma unroll
    for (int i = 0; i < 4; i++)
        #pragma unroll
        for (int j = 0; j < 4; j++)
            #pragma unroll
            for (int q = 0; q < 4; q++) acc[i][j][q] = 0.0f;

    const int niter = K >> 5;

    /* stage loader: 2 rows x 16B per thread into buffer buf */
    auto stageLoad = [&](int k0, int buf) {
        int k = k0 + scc*8;
        #pragma unroll
        for (int j = 0; j < 2; j++) {
            int row = srow + j*64;
            const __half* srcA;
            if (aMode == 0)       srcA = A + (size_t)(m0+row)*ldw + k;
            else {
                int4 ri = rowinfo[row];
                if (aMode == 3)     srcA = g_inputs + ri.x + k;
                else if (k < 128)   srcA = g_enc + (size_t)ri.y + k;
                else if (k < 160)   srcA = g_inputs + ri.x + (k-128);
                else                srcA = g_extra + (size_t)ri.z + (k-160);
            }
            uint32_t off = (uint32_t)((row*40 + scc*8)*2) + (uint32_t)buf*GSTG_B;
            cpa16(aS + off, srcA);
            cpa16(bS + off, W + (size_t)(n0+row)*ldw + k);
        }
    };

    stageLoad(0, 0);
    cpa_commit();

    for (int it = 0; it < niter; it++) {
        if (it+1 < niter) {
            stageLoad((it+1)*32, (it+1)&1);
            cpa_commit();
            asm volatile("cp.async.wait_group 1;");
        } else {
            asm volatile("cp.async.wait_group 0;");
        }
        __syncthreads();
        uint32_t bo = (uint32_t)(it&1)*GSTG_B;
        #pragma unroll
        for (int kk = 0; kk < 2; kk++) {
            uint32_t a[4][4];
            #pragma unroll
            for (int mi = 0; mi < 4; mi++) ldsm4(a[mi], aAddr[mi] + bo + kk*32);
            #pragma unroll
            for (int nig = 0; nig < 2; nig++) {
                uint32_t bb[4];
                ldsm4(bb, bAddr[nig] + bo + kk*32);
                #pragma unroll
                for (int mi = 0; mi < 4; mi++) {
                    mma16(acc[mi][nig*2],   a[mi], bb[0], bb[1]);
                    mma16(acc[mi][nig*2+1], a[mi], bb[2], bb[3]);
                }
            }
        }
        __syncthreads();
    }

    if (epi == 0) {
        #pragma unroll
        for (int mi = 0; mi < 4; mi++) {
            int row = m0 + wm*64 + mi*16 + g;
            #pragma unroll
            for (int ni = 0; ni < 4; ni++) {
                int col = n0 + wn*32 + ni*8 + 2*tig;
                float b0 = bias[col], b1 = bias[col+1];
                *(__half2*)&C[(size_t)row*512 + col] =
                    __floats2half2_rn(acc[mi][ni][0]+b0, acc[mi][ni][1]+b1);
                *(__half2*)&C[(size_t)(row+8)*512 + col] =
                    __floats2half2_rn(acc[mi][ni][2]+b0, acc[mi][ni][3]+b1);
            }
        }
    } else {
        #pragma unroll
        for (int mi = 0; mi < 4; mi++) {
            int rowb = m0 + wm*64 + mi*16 + g;
            #pragma unroll
            for (int ni = 0; ni < 4; ni++) {
                int col = n0 + wn*32 + ni*8 + 2*tig;
                float b0 = bias[col], b1 = bias[col+1];
                float c0 = acc[mi][ni][0] + b0;
                float c1 = acc[mi][ni][1] + b1;
                float c2 = acc[mi][ni][2] + b0;
                float c3 = acc[mi][ni][3] + b1;
                float r0 = __shfl_xor_sync(0xffffffffu, c0, 1);
                float r1 = __shfl_xor_sync(0xffffffffu, c1, 1);
                float r2 = __shfl_xor_sync(0xffffffffu, c2, 1);
                float r3 = __shfl_xor_sync(0xffffffffu, c3, 1);
                int u = col >> 2;
                int row; float rg, zg, ing, hng;
                if ((tig & 1) == 0) { rg = c0; zg = c1; ing = r0; hng = r1; row = rowb; }
                else                { ing = c2; hng = c3; rg = r2; zg = r3; row = rowb+8; }
                float rr = sigm_fast(rg), zz = sigm_fast(zg);
                float nn = tanh_fast(ing + rr*hng);
                float hold = zeroH ? 0.0f : __half2float(g_enc[(size_t)row*NC + u]);
                g_hv[(size_t)row*NC + u] = __float2half((1.0f - zz)*nn + zz*hold);
            }
        }
    }
}

/* ------------------------------------------------------------------ */
/* fused fp16 LSTM sequence: Whh resident, Hs ping-pong (1 sync/step), */
/* acc initialized from xw (gate-adds folded into MMA accumulators).   */
/* 64 rows/block, 512 thr (16 warps 2x8, warp tile 32x64).             */
/* ------------------------------------------------------------------ */
__global__ __launch_bounds__(512) void lstm_seq(
    const __half* __restrict__ Whh,   /* packed [512][128] */
    const __half* __restrict__ xw,    /* [NROWS][512] fp16, bias folded */
    __half*       __restrict__ ys,
    int initHC)
{
    extern __shared__ __align__(16) __half smem[];
    __half* Ws = smem;                 /* 512 x WS_PAD */
    __half* Hs = smem + 512*WS_PAD;    /* 2 x 64x128 swizzled */

    int tid = threadIdx.x;
    int b0 = blockIdx.x*64;
    int w = tid>>5, lane = tid&31;
    int wm = w>>3, wn = w&7;
    int g = lane>>2, tig = lane&3;

    /* load Whh once */
    #pragma unroll
    for (int i = 0; i < 16; i++) {
        int idx = tid + i*512;
        int row = idx >> 4, ch = idx & 15;
        *(int4*)(Ws + row*WS_PAD + ch*8) =
            *(const int4*)(Whh + (size_t)row*128 + ch*8);
    }
    /* init h into buffer 0 */
    for (int i = tid; i < 64*128; i += 512) {
        int m = i>>7, k = i&127;
        float hv = initHC ? 0.0f : g_h0[(b0+m)*NC + k];
        Hs[m*128 + (((k>>3) ^ (m&7))<<3) + (k&7)] = __float2half(hv);
    }
    float c_reg[16];
    #pragma unroll
    for (int mi = 0; mi < 2; mi++)
        #pragma unroll
        for (int ni = 0; ni < 8; ni++) {
            int rowl = wm*32 + mi*16 + g + ((tig & 1) ? 8 : 0);
            int u    = (wn*64 + ni*8 + 2*tig) >> 2;
            c_reg[mi*8+ni] = initHC ? 0.0f : g_c[(b0+rowl)*NC + u];
        }

    uint32_t hBase[2]; int hS[2]; int hCh = lane>>4;
    {
        int rl = lane&15;
        #pragma unroll
        for (int mi = 0; mi < 2; mi++) {
            int r = wm*32 + mi*16 + rl;
            hBase[mi] = (uint32_t)__cvta_generic_to_shared(Hs + r*128);
            hS[mi] = r & 7;
        }
    }
    uint32_t bAddr[4];
    {
        int rb0 = (lane&7) + ((lane&16)>>1);
        int cb  = (lane>>3)&1;
        #pragma unroll
        for (int nig = 0; nig < 4; nig++) {
            int r = wn*64 + nig*16 + rb0;
            bAddr[nig] = (uint32_t)__cvta_generic_to_shared(Ws + r*WS_PAD + cb*8);
        }
    }
    __syncthreads();

    for (int t = 0; t < SP; t++) {
        /* accumulators pre-loaded with xw gates (loads hide under MMA) */
        float acc[2][8][4];
        #pragma unroll
        for (int mi = 0; mi < 2; mi++) {
            int rbl = wm*32 + mi*16 + g;
            #pragma unroll
            for (int ni = 0; ni < 8; ni++) {
                int col = wn*64 + ni*8 + 2*tig;
                size_t x0 = ((size_t)(b0+rbl  )*SP + t)*512 + col;
                size_t x1 = ((size_t)(b0+rbl+8)*SP + t)*512 + col;
                float2 v0 = __half22float2(*(const __half2*)&xw[x0]);
                float2 v1 = __half22float2(*(const __half2*)&xw[x1]);
                acc[mi][ni][0] = v0.x;  acc[mi][ni][1] = v0.y;
                acc[mi][ni][2] = v1.x;  acc[mi][ni][3] = v1.y;
            }
        }

        uint32_t rOff = (uint32_t)(t&1)*16384u;   /* read buffer */
        #pragma unroll
        for (int kk = 0; kk < 8; kk++) {
            uint32_t a[2][4];
            #pragma unroll
            for (int mi = 0; mi < 2; mi++) {
                uint32_t ad = hBase[mi] + rOff +
                              (uint32_t)((((2*kk + hCh) ^ hS[mi]))<<4);
                ldsm4(a[mi], ad);
            }
            #pragma unroll
            for (int nig = 0; nig < 4; nig++) {
                uint32_t bb[4];
                ldsm4(bb, bAddr[nig] + kk*32);
                mma16(acc[0][nig*2],   a[0], bb[0], bb[1]);
                mma16(acc[1][nig*2],   a[1], bb[0], bb[1]);
                mma16(acc[0][nig*2+1], a[0], bb[2], bb[3]);
                mma16(acc[1][nig*2+1], a[1], bb[2], bb[3]);
            }
        }

        /* epilogue: gate exchange, cell update; write h into other buf */
        __half* Hn = Hs + ((t&1)^1)*8192;
        #pragma unroll
        for (int mi = 0; mi < 2; mi++) {
            int rbl = wm*32 + mi*16 + g;
            #pragma unroll
            for (int ni = 0; ni < 8; ni++) {
                int col = wn*64 + ni*8 + 2*tig;
                float c0 = acc[mi][ni][0];
                float c1 = acc[mi][ni][1];
                float c2 = acc[mi][ni][2];
                float c3 = acc[mi][ni][3];
                float r0 = __shfl_xor_sync(0xffffffffu, c0, 1);
                float r1 = __shfl_xor_sync(0xffffffffu, c1, 1);
                float r2 = __shfl_xor_sync(0xffffffffu, c2, 1);
                float r3 = __shfl_xor_sync(0xffffffffu, c3, 1);
                int u = col >> 2;
                int rowl; float ig, fg, gg, og;
                if ((tig & 1) == 0) { ig = c0; fg = c1; gg = r0; og = r1; rowl = rbl; }
                else                { gg = c2; og = c3; ig = r2; fg = r3; rowl = rbl+8; }
                float cold = c_reg[mi*8+ni];
                float cn = sigm_fast(fg)*cold + sigm_fast(ig)*tanh_fast(gg);
                float hn = sigm_fast(og)*tanh_fast(cn);
                c_reg[mi*8+ni] = cn;
                __half hh = __float2half(hn);
                Hn[rowl*128 + (((u>>3) ^ (rowl&7))<<3) + (u&7)] = hh;
                ys[((size_t)(b0+rowl)*SP + t)*NC + u] = hh;
            }
        }
        __syncthreads();   /* Hn visible before next step's ldsm */
    }

    /* final h is in buffer 0 (24 steps, writes ended in buf 0) */
    for (int i = tid; i < 64*128; i += 512) {
        int m = i>>7, k = i&127;
        g_h0[(b0+m)*NC + k] =
            __half2float(Hs[m*128 + (((k>>3) ^ (m&7))<<3) + (k&7)]);
    }
    #pragma unroll
    for (int mi = 0; mi < 2; mi++)
        #pragma unroll
        for (int ni = 0; ni < 8; ni++) {
            int rowl = wm*32 + mi*16 + g + ((tig & 1) ? 8 : 0);
            int u    = (wn*64 + ni*8 + 2*tig) >> 2;
            g_c[(b0+rowl)*NC + u] = c_reg[mi*8+ni];
        }
}

/* ---------------- output projection + rescale ---------------------- */
__global__ void out_kernel(const float* __restrict__ oW,
                           const float* __restrict__ ob,
                           float* __restrict__ out)
{
    int r    = blockIdx.x*8 + (threadIdx.x >> 5);
    int lane = threadIdx.x & 31;
    float s = 0.0f;
    #pragma unroll
    for (int k = 0; k < 4; k++)
        s += __half2float(g_dech[(size_t)r*NC + lane + 32*k])*oW[lane + 32*k];
    #pragma unroll
    for (int o = 16; o; o >>= 1) s += __shfl_down_sync(0xffffffffu, s, o);
    if (lane == 0)
        out[r] = (s + ob[0])*g_scale[r/SP];
}

/* ---------------- host driver -------------------------------------- */
extern "C" void kernel_launch(void* const* d_in, const int* in_sizes, int n_in,
                              void* d_out, int out_size)
{
    const int*   cat   = (const int*)  d_in[0];
    const float* sreal = (const float*)d_in[1];
    const float* ptf   = (const float*)d_in[2];
    const float* pt    = (const float*)d_in[3];
    const float* pov   = (const float*)d_in[4];
    const float* ftf   = (const float*)d_in[5];
    const float* emb   = (const float*)d_in[6];
    const float* gWih  = (const float*)d_in[7];
    const float* gWhh  = (const float*)d_in[8];
    const float* gbih  = (const float*)d_in[9];
    const float* gbhh  = (const float*)d_in[10];
    const float* eWih  = (const float*)d_in[11];
    const float* eWhh  = (const float*)d_in[12];
    const float* eb    = (const float*)d_in[13];
    const float* dWih  = (const float*)d_in[14];
    const float* dWhh  = (const float*)d_in[15];
    const float* db    = (const float*)d_in[16];
    const float* oW    = (const float*)d_in[17];
    const float* ob    = (const float*)d_in[18];
    float* out = (float*)d_out;

    float *p_bcat, *p_eb, *p_db;
    __half *p_xw, *p_hv, *p_enc, *p_dech, *p_Wcat, *p_eWih, *p_eWhh, *p_dWih, *p_dWhh;
    cudaGetSymbolAddress((void**)&p_xw,   g_xw);
    cudaGetSymbolAddress((void**)&p_hv,   g_hv);
    cudaGetSymbolAddress((void**)&p_enc,  g_enc);
    cudaGetSymbolAddress((void**)&p_dech, g_dech);
    cudaGetSymbolAddress((void**)&p_Wcat, g_Wcat);
    cudaGetSymbolAddress((void**)&p_bcat, g_bcat);
    cudaGetSymbolAddress((void**)&p_eWih, g_eWih);
    cudaGetSymbolAddress((void**)&p_eWhh, g_eWhh);
    cudaGetSymbolAddress((void**)&p_eb,   g_eb);
    cudaGetSymbolAddress((void**)&p_dWih, g_dWih);
    cudaGetSymbolAddress((void**)&p_dWhh, g_dWhh);
    cudaGetSymbolAddress((void**)&p_db,   g_db);

    static int smem_set = 0;
    if (!smem_set) {
        cudaFuncSetAttribute(lstm_seq,
            cudaFuncAttributeMaxDynamicSharedMemorySize, LSTM_SMEM);
        smem_set = 1;
    }

    dim3 gGrid(NROWS/128, 4), gThr(256);

    row_stats<<<BATCH/8, 256>>>(pt, pov);
    pack_gru<<<(512*KCAT + 255)/256, 256>>>(gWih, gWhh, gbih, gbhh);
    pack_enc<<<(NSEG*512*128 + 255)/256, 256>>>(eWih, eWhh, eb);
    build_inputs<<<BATCH, 192>>>(cat, sreal, ptf, pt, emb);

    /* seg 0: GRU over x only (h==0), K=32 */
    gemm_fp16<<<gGrid, gThr>>>(3, 0, nullptr, 32, KCAT,
                               p_Wcat + 128, p_bcat, nullptr, 1, 1);
    /* seg 0 LSTM input projection */
    gemm_fp16<<<gGrid, gThr>>>(0, 0, p_hv, NC, NC,
                               p_eWih, p_eb, p_xw, 0, 0);
    build_extra<<<(NROWS + 255)/256, 256>>>(ftf);
    pack_dec<<<(512*KQP + 255)/256, 256>>>(dWih, dWhh, db);
    lstm_seq<<<BATCH/64, 512, LSTM_SMEM>>>(p_eWhh, p_xw, p_enc, 1);

    for (int i = 1; i < NSEG; i++) {
        gemm_fp16<<<gGrid, gThr>>>(1, i, nullptr, KCAT, KCAT,
                                   p_Wcat, p_bcat, nullptr, 1, 0);
        gemm_fp16<<<gGrid, gThr>>>(0, 0, p_hv, NC, NC,
                                   p_eWih + (size_t)i*512*128,
                                   p_eb + i*512, p_xw, 0, 0);
        lstm_seq<<<BATCH/64, 512, LSTM_SMEM>>>(p_eWhh + (size_t)i*512*128,
                                               p_xw, p_enc, 0);
    }

    /* decoder: query [enc|x|extra], K=192 */
    gemm_fp16<<<gGrid, gThr>>>(2, 0, nullptr, KQP, KQP,
                               p_dWih, p_db, p_xw, 0, 0);
    lstm_seq<<<BATCH/64, 512, LSTM_SMEM>>>(p_dWhh, p_xw, p_dech, 0);

    out_kernel<<<NROWS/8, 256>>>(oW, ob, out);
}